// round 9
// baseline (speedup 1.0000x reference)
#include <cuda_runtime.h>
#include <cuda_fp16.h>
#include <cstdint>

// Problem constants
#define Bb 128
#define Ss 128
#define Hh 1024
#define Ee 512
#define Vv 32000

// fp16 GEMM tile config: CTA 128x128, 4 warps, warp tile 64x64, BK=32, 3 stages
#define BM 128
#define BN 128
#define BK 32
#define SAH 40                       // padded smem row stride in halfs (80B rows)
#define TILE_H (BM * SAH)            // 5120 halfs per A or B tile
#define STAGE_H (2 * TILE_H)         // 10240 halfs per stage
#define NSTG 3
#define DSMEM_BYTES (NSTG * STAGE_H * 2)   // 61440

// ---------------- scratch (device globals; no allocation allowed) ----------
__device__ __align__(256) __half g_ench[(size_t)Ss * Bb * 2 * Hh]; // enc fp16
__device__ __align__(256) __half g_w1e[Hh * 2 * Hh];               // W1[:, :2048] fp16
__device__ __align__(256) __half g_dhh[Bb * Hh];                   // dh fp16
__device__ __align__(256) __half g_xh[Bb * 2560];                  // [embeds | a] fp16
__device__ __align__(256) __half g_c1h[Bb * 3584];                 // [h | a | emb] fp16
__device__ __align__(256) float  g_hb[Bb * Hh];
__device__ __align__(256) float  g_part[8 * Ss * Bb];
__device__ __align__(256) float  g_alpha[Ss * Bb];
__device__ __align__(256) float  g_gx[Bb * 3 * Hh];
__device__ __align__(256) float  g_gh[Bb * 3 * Hh];

// ---------------- helpers ---------------------------------------------------
__device__ __forceinline__ uint32_t smem_u32(const void* p) {
    uint32_t a;
    asm("{ .reg .u64 t; cvta.to.shared.u64 t, %1; cvt.u32.u64 %0, t; }"
        : "=r"(a) : "l"(p));
    return a;
}

__device__ __forceinline__ void mma_f16(float* c,
                                        uint32_t a0, uint32_t a1, uint32_t a2, uint32_t a3,
                                        uint32_t b0, uint32_t b1) {
    asm volatile(
        "mma.sync.aligned.m16n8k16.row.col.f32.f16.f16.f32 "
        "{%0,%1,%2,%3}, {%4,%5,%6,%7}, {%8,%9}, {%0,%1,%2,%3};"
        : "+f"(c[0]), "+f"(c[1]), "+f"(c[2]), "+f"(c[3])
        : "r"(a0), "r"(a1), "r"(a2), "r"(a3), "r"(b0), "r"(b1));
}

__device__ __forceinline__ void ldsm4(uint32_t& r0, uint32_t& r1,
                                      uint32_t& r2, uint32_t& r3, uint32_t addr) {
    asm volatile("ldmatrix.sync.aligned.m8n8.x4.shared.b16 {%0,%1,%2,%3}, [%4];"
                 : "=r"(r0), "=r"(r1), "=r"(r2), "=r"(r3) : "r"(addr));
}

__device__ __forceinline__ void cp16u(uint32_t dst, const void* src) {
    asm volatile("cp.async.ca.shared.global [%0], [%1], 16;" :: "r"(dst), "l"(src));
}
__device__ __forceinline__ void cp_commit() {
    asm volatile("cp.async.commit_group;" ::: "memory");
}
template <int N>
__device__ __forceinline__ void cp_wait() {
    asm volatile("cp.async.wait_group %0;" :: "n"(N) : "memory");
}

__device__ __forceinline__ float tanh_fast(float x) {
    x = fminf(10.f, fmaxf(-10.f, x));
    const float t = __expf(2.f * x);
    return (t - 1.f) / (t + 1.f);
}

__device__ __forceinline__ uint2 cvt_f4_h4(float4 v) {
    half2 h0 = __floats2half2_rn(v.x, v.y);
    half2 h1 = __floats2half2_rn(v.z, v.w);
    uint2 u;
    u.x = *reinterpret_cast<uint32_t*>(&h0);
    u.y = *reinterpret_cast<uint32_t*>(&h1);
    return u;
}

// ---------------- GEMM compute body: ldmatrix + m16n8k16 --------------------
__device__ __forceinline__ void compute_kb(uint32_t aBase, uint32_t bBase,
                                           float c[4][8][4], int wm, int wn,
                                           uint32_t aOff, uint32_t bOff) {
#pragma unroll
    for (int ks = 0; ks < 2; ks++) {
        const uint32_t k0b = ks * 32;   // 16 halfs
        uint32_t af[4][4], bf[4][4];
#pragma unroll
        for (int mf = 0; mf < 4; mf++)
            ldsm4(af[mf][0], af[mf][1], af[mf][2], af[mf][3],
                  aBase + (uint32_t)(((wm * 64 + mf * 16) * SAH) * 2) + k0b + aOff);
#pragma unroll
        for (int np = 0; np < 4; np++)
            ldsm4(bf[np][0], bf[np][1], bf[np][2], bf[np][3],
                  bBase + (uint32_t)(((wn * 64 + np * 16) * SAH) * 2) + k0b + bOff);
#pragma unroll
        for (int nf = 0; nf < 8; nf++) {
            const uint32_t b0 = bf[nf >> 1][(nf & 1) << 1];
            const uint32_t b1 = bf[nf >> 1][((nf & 1) << 1) + 1];
#pragma unroll
            for (int mf = 0; mf < 4; mf++)
                mma_f16(c[mf][nf], af[mf][0], af[mf][1], af[mf][2], af[mf][3], b0, b1);
        }
    }
}

// ---------------- epilogues --------------------------------------------------
// EPI 0: out = acc + bias   EPI 1: energy reduce   EPI 2: out += acc
template <int EPI>
__device__ __forceinline__ void epilogue(float c[4][8][4],
                                         const float* __restrict__ bias,
                                         float* __restrict__ out,
                                         int M, int ldc, int m0, int n0,
                                         const float* __restrict__ hb,
                                         const float* __restrict__ W2,
                                         float (*red)[2],
                                         int tid, int wm, int wn, int r, int q,
                                         int bx) {
    if (EPI == 0 || EPI == 2) {
#pragma unroll
        for (int mf = 0; mf < 4; mf++)
#pragma unroll
            for (int rr = 0; rr < 2; rr++) {
                const int mg = m0 + wm * 64 + mf * 16 + rr * 8 + r;
#pragma unroll
                for (int nf = 0; nf < 8; nf++) {
                    const int ng = n0 + wn * 64 + nf * 8 + q * 2;
                    float* p = &out[(size_t)mg * ldc + ng];
                    float2 v;
                    if (EPI == 0) {
                        v.x = c[mf][nf][rr * 2 + 0] + bias[ng];
                        v.y = c[mf][nf][rr * 2 + 1] + bias[ng + 1];
                    } else {
                        float2 o = *(float2*)p;
                        v.x = o.x + c[mf][nf][rr * 2 + 0];
                        v.y = o.y + c[mf][nf][rr * 2 + 1];
                    }
                    *(float2*)p = v;
                }
            }
    } else {
        float rs[4][2];
#pragma unroll
        for (int mf = 0; mf < 4; mf++)
#pragma unroll
            for (int rr = 0; rr < 2; rr++) {
                const int row = wm * 64 + mf * 16 + rr * 8 + r; // == b
                float acc = 0.f;
#pragma unroll
                for (int nf = 0; nf < 8; nf++) {
                    const int ng = n0 + wn * 64 + nf * 8 + q * 2;
                    const float h0 = hb[row * Hh + ng];
                    const float h1 = hb[row * Hh + ng + 1];
                    acc += tanh_fast(c[mf][nf][rr * 2 + 0] + h0) * W2[ng];
                    acc += tanh_fast(c[mf][nf][rr * 2 + 1] + h1) * W2[ng + 1];
                }
                rs[mf][rr] = acc;
            }
#pragma unroll
        for (int mf = 0; mf < 4; mf++)
#pragma unroll
            for (int rr = 0; rr < 2; rr++) {
                rs[mf][rr] += __shfl_xor_sync(0xffffffffu, rs[mf][rr], 1);
                rs[mf][rr] += __shfl_xor_sync(0xffffffffu, rs[mf][rr], 2);
            }
        if (q == 0) {
#pragma unroll
            for (int mf = 0; mf < 4; mf++)
#pragma unroll
                for (int rr = 0; rr < 2; rr++)
                    red[wm * 64 + mf * 16 + rr * 8 + r][wn] = rs[mf][rr];
        }
        __syncthreads();
        if (tid < BM)
            out[(size_t)bx * M + m0 + tid] = red[tid][0] + red[tid][1];
    }
}

// ---------------- mainloops (device functions, explicit m0/n0) --------------
// HH: A fp16, B fp16 (both cp.async)
__device__ __forceinline__ void mainloop_hh(const __half* __restrict__ A,
                                            const __half* __restrict__ Bw,
                                            int K, int lda, int ldb,
                                            int m0, int n0,
                                            float c[4][8][4], __half* dynh,
                                            int tid, int wm, int wn,
                                            uint32_t aOff, uint32_t bOff) {
    const int nK = K / BK;
    const uint32_t dynU = smem_u32(dynh);
    auto cpfill = [&](int kb, int stg) {
        const uint32_t base = dynU + stg * (STAGE_H * 2);
        const int ko = kb * BK;
#pragma unroll
        for (int h = 0; h < 4; h++) {
            const int cc = tid + h * 128;
            const int row = cc >> 2, g = cc & 3;
            cp16u(base + (row * SAH + g * 8) * 2,
                  A + (size_t)(m0 + row) * lda + ko + g * 8);
            cp16u(base + TILE_H * 2 + (row * SAH + g * 8) * 2,
                  Bw + (size_t)(n0 + row) * ldb + ko + g * 8);
        }
    };
    cpfill(0, 0); cp_commit();
    cpfill(1, 1); cp_commit();
    cp_wait<1>(); __syncthreads();
    int stg = 0;
    for (int kb = 0; kb < nK; kb++) {
        if (kb + 2 < nK) {
            int s2 = stg + 2; if (s2 >= NSTG) s2 -= NSTG;
            cpfill(kb + 2, s2);
        }
        cp_commit();
        const uint32_t aB = dynU + stg * (STAGE_H * 2);
        compute_kb(aB, aB + TILE_H * 2, c, wm, wn, aOff, bOff);
        cp_wait<1>(); __syncthreads();
        if (++stg == NSTG) stg = 0;
    }
}

// HF: A fp16 (cp.async), B fp32 (LDG -> cvt -> STS)
__device__ __forceinline__ void mainloop_hf(const __half* __restrict__ A,
                                            const float* __restrict__ Bw,
                                            int K, int lda, int ldb,
                                            int m0, int n0,
                                            float c[4][8][4], __half* dynh,
                                            int tid, int wm, int wn,
                                            uint32_t aOff, uint32_t bOff) {
    const int nK = K / BK;
    const uint32_t dynU = smem_u32(dynh);
    int rowv[8], gv[8];
#pragma unroll
    for (int h = 0; h < 8; h++) {
        const int idx = tid + h * 128;
        rowv[h] = idx >> 3;
        gv[h]   = idx & 7;
    }
    uint2 sb[8];
    auto cpA = [&](int kb, int stg) {
        const uint32_t base = dynU + stg * (STAGE_H * 2);
        const int ko = kb * BK;
#pragma unroll
        for (int h = 0; h < 4; h++) {
            const int cc = tid + h * 128;
            const int row = cc >> 2, g = cc & 3;
            cp16u(base + (row * SAH + g * 8) * 2,
                  A + (size_t)(m0 + row) * lda + ko + g * 8);
        }
    };
    auto ldB = [&](int kb) {
        const int ko = kb * BK;
#pragma unroll
        for (int h = 0; h < 8; h++)
            sb[h] = cvt_f4_h4(*(const float4*)(Bw + (size_t)(n0 + rowv[h]) * ldb
                                               + ko + gv[h] * 4));
    };
    auto stsB = [&](int stg) {
        __half* D = dynh + stg * STAGE_H + TILE_H;
#pragma unroll
        for (int h = 0; h < 8; h++)
            *(uint2*)(D + rowv[h] * SAH + gv[h] * 4) = sb[h];
    };
    cpA(0, 0); cp_commit();
    cpA(1, 1); cp_commit();
    ldB(0); stsB(0); ldB(1);
    cp_wait<1>(); __syncthreads();
    int stg = 0;
    for (int kb = 0; kb < nK; kb++) {
        int w = stg + 1; if (w == NSTG) w = 0;
        if (kb + 1 < nK) stsB(w);
        if (kb + 2 < nK) {
            int s2 = stg + 2; if (s2 >= NSTG) s2 -= NSTG;
            cpA(kb + 2, s2);
            ldB(kb + 2);
        }
        cp_commit();
        const uint32_t aB = dynU + stg * (STAGE_H * 2);
        compute_kb(aB, aB + TILE_H * 2, c, wm, wn, aOff, bOff);
        cp_wait<1>(); __syncthreads();
        stg = w;
    }
}

// FF: A fp32 and B fp32, both LDG -> cvt -> STS (no pre-converted operands)
__device__ __forceinline__ void mainloop_ff(const float* __restrict__ A,
                                            const float* __restrict__ Bw,
                                            int K, int lda, int ldb,
                                            int m0, int n0,
                                            float c[4][8][4], __half* dynh,
                                            int tid, int wm, int wn,
                                            uint32_t aOff, uint32_t bOff) {
    const int nK = K / BK;
    int rowv[8], gv[8];
#pragma unroll
    for (int h = 0; h < 8; h++) {
        const int idx = tid + h * 128;
        rowv[h] = idx >> 3;
        gv[h]   = idx & 7;
    }
    uint2 sa[8], sb[8];
    auto ldAB = [&](int kb) {
        const int ko = kb * BK;
#pragma unroll
        for (int h = 0; h < 8; h++) {
            sa[h] = cvt_f4_h4(*(const float4*)(A  + (size_t)(m0 + rowv[h]) * lda
                                               + ko + gv[h] * 4));
            sb[h] = cvt_f4_h4(*(const float4*)(Bw + (size_t)(n0 + rowv[h]) * ldb
                                               + ko + gv[h] * 4));
        }
    };
    auto stsAB = [&](int stg) {
        __half* D = dynh + stg * STAGE_H;
#pragma unroll
        for (int h = 0; h < 8; h++) {
            *(uint2*)(D + rowv[h] * SAH + gv[h] * 4)          = sa[h];
            *(uint2*)(D + TILE_H + rowv[h] * SAH + gv[h] * 4) = sb[h];
        }
    };
    ldAB(0); stsAB(0);
    if (nK > 1) ldAB(1);
    __syncthreads();
    int stg = 0;
    for (int kb = 0; kb < nK; kb++) {
        int w = stg + 1; if (w == NSTG) w = 0;
        if (kb + 1 < nK) stsAB(w);
        if (kb + 2 < nK) ldAB(kb + 2);
        compute_kb(smem_u32(dynh) + stg * (STAGE_H * 2),
                   smem_u32(dynh) + stg * (STAGE_H * 2) + TILE_H * 2,
                   c, wm, wn, aOff, bOff);
        __syncthreads();
        stg = w;
    }
}

#define GEMM_PREAMBLE \
    extern __shared__ __align__(16) __half dynh[]; \
    __shared__ float red[BM][2]; \
    const int tid = threadIdx.x, lane = tid & 31, wid = tid >> 5; \
    const int wm = wid >> 1, wn = wid & 1, r = lane >> 2, q = lane & 3; \
    const uint32_t aOff = (uint32_t)((((lane & 15) * SAH) + (lane >> 4) * 8) * 2); \
    const uint32_t bOff = (uint32_t)(((((lane >> 4) * 8 + (lane & 7)) * SAH) \
                                      + ((lane >> 3) & 1) * 8) * 2); \
    float c[4][8][4]; \
    _Pragma("unroll") for (int i = 0; i < 4; i++) \
    _Pragma("unroll") for (int j = 0; j < 8; j++) \
    _Pragma("unroll") for (int k = 0; k < 4; k++) c[i][j][k] = 0.f;

// ============================================================================
// k_prep: one launch for all prep work. Roles by blockIdx.x (128 threads each):
//   [0, 4096)        enc -> fp16        (2048 float4 per block)
//   [4096, 4608)     W1[:, :2048] -> fp16 (1024 float4 per block)
//   [4608, 4624)     dh -> fp16         (2048 float4 per block)
//   [4624, 4752)     embeddings -> xh, c1h (one b per block)
//   [4752, 4760)     hb GEMM (FF, 8 n-tiles): hb = dh @ W1h^T + b1
// ============================================================================
#define ENC_B 4096
#define W1E_B 512
#define DH_B  16
#define EMB_B 128

__global__ __launch_bounds__(128, 2)
void k_prep(const float* __restrict__ enc, __half* __restrict__ ench,
            const float* __restrict__ W1, __half* __restrict__ w1e,
            const float* __restrict__ dh, __half* __restrict__ dhh,
            const int* __restrict__ tl, const float* __restrict__ emb,
            __half* __restrict__ xh, __half* __restrict__ c1h,
            const float* __restrict__ b1, float* __restrict__ hb) {
    const int bid = blockIdx.x;
    if (bid < ENC_B) {
        const float4* src = (const float4*)enc;
        uint2* dst = (uint2*)ench;
        const int base = bid * 2048 + threadIdx.x;
#pragma unroll
        for (int j = 0; j < 16; j++)
            dst[base + j * 128] = cvt_f4_h4(src[base + j * 128]);
    } else if (bid < ENC_B + W1E_B) {
        const int base = (bid - ENC_B) * 1024 + threadIdx.x;
#pragma unroll
        for (int j = 0; j < 8; j++) {
            const int i = base + j * 128;           // f4 index in w1e
            const int row = i >> 9, c4 = i & 511;
            float4 v = *(const float4*)(W1 + (size_t)row * 3072 + c4 * 4);
            *(uint2*)(w1e + row * 2048 + c4 * 4) = cvt_f4_h4(v);
        }
    } else if (bid < ENC_B + W1E_B + DH_B) {
        const float4* src = (const float4*)dh;
        uint2* dst = (uint2*)dhh;
        const int base = (bid - ENC_B - W1E_B) * 2048 + threadIdx.x;
#pragma unroll
        for (int j = 0; j < 16; j++)
            dst[base + j * 128] = cvt_f4_h4(src[base + j * 128]);
    } else if (bid < ENC_B + W1E_B + DH_B + EMB_B) {
        const int b = bid - ENC_B - W1E_B - DH_B;
        const size_t rowoff = (size_t)tl[b] * Ee;
#pragma unroll
        for (int j = 0; j < 4; j++) {
            const int e = threadIdx.x + j * 128;
            const __half v = __float2half_rn(emb[rowoff + e]);
            xh[b * 2560 + e] = v;
            c1h[b * 3584 + 3072 + e] = v;
        }
    } else {
        GEMM_PREAMBLE
        const int n0 = (bid - ENC_B - W1E_B - DH_B - EMB_B) * BN;
        mainloop_ff(dh, W1 + 2048, Hh, Hh, 3 * Hh, 0, n0,
                    c, dynh, tid, wm, wn, aOff, bOff);
        epilogue<0>(c, b1, hb, Bb, Hh, 0, n0, nullptr, nullptr, red,
                    tid, wm, wn, r, q, 0);
    }
}

// ============================================================================
// merged1: [0,1024) energy (hh, EPI1) ; [1024,1274) pred-embeds (hf, EPI0) ;
//          [1274,1298) gh (hf, EPI0)
// ============================================================================
__global__ __launch_bounds__(128, 2)
void k_merged1(const __half* __restrict__ ench, const __half* __restrict__ w1e,
               const float* __restrict__ hb, const float* __restrict__ W2,
               float* __restrict__ part,
               const __half* __restrict__ c1h, const float* __restrict__ Wout,
               const float* __restrict__ bout, float* __restrict__ pred,
               const __half* __restrict__ dhh, const float* __restrict__ Whh,
               const float* __restrict__ bhh, float* __restrict__ gh) {
    GEMM_PREAMBLE
    const int bid = blockIdx.x;
    if (bid < 1024) {
        const int n0 = (bid & 7) * BN, m0 = (bid >> 3) * BM;
        mainloop_hh(ench, w1e, 2 * Hh, 2 * Hh, 2 * Hh, m0, n0,
                    c, dynh, tid, wm, wn, aOff, bOff);
        epilogue<1>(c, nullptr, part, Ss * Bb, 0, m0, n0, hb, W2, red,
                    tid, wm, wn, r, q, bid & 7);
    } else if (bid < 1274) {
        const int n0 = (bid - 1024) * BN;
        mainloop_hf(c1h + 3072, Wout + 3072, Ee, 3584, 3584, 0, n0,
                    c, dynh, tid, wm, wn, aOff, bOff);
        epilogue<0>(c, bout, pred, Bb, Vv, 0, n0, nullptr, nullptr, red,
                    tid, wm, wn, r, q, 0);
    } else {
        const int n0 = (bid - 1274) * BN;
        mainloop_hf(dhh, Whh, Hh, Hh, Hh, 0, n0,
                    c, dynh, tid, wm, wn, aOff, bOff);
        epilogue<0>(c, bhh, gh, Bb, 3 * Hh, 0, n0, nullptr, nullptr, red,
                    tid, wm, wn, r, q, 0);
    }
}

// ============================================================================
// merged2: [0,24) gx ; [24,274) pred-a (EPI2 add) — 274 CTAs = single wave
// ============================================================================
__global__ __launch_bounds__(128, 2)
void k_merged2(const __half* __restrict__ xh, const float* __restrict__ Wih,
               const float* __restrict__ bih, float* __restrict__ gx,
               const __half* __restrict__ c1h, const float* __restrict__ Wout,
               float* __restrict__ pred) {
    GEMM_PREAMBLE
    const int bid = blockIdx.x;
    if (bid < 24) {
        const int n0 = bid * BN;
        mainloop_hf(xh, Wih, 2560, 2560, 2560, 0, n0,
                    c, dynh, tid, wm, wn, aOff, bOff);
        epilogue<0>(c, bih, gx, Bb, 3 * Hh, 0, n0, nullptr, nullptr, red,
                    tid, wm, wn, r, q, 0);
    } else {
        const int n0 = (bid - 24) * BN;
        mainloop_hf(c1h + 1024, Wout + 1024, 2 * Hh, 3584, 3584, 0, n0,
                    c, dynh, tid, wm, wn, aOff, bOff);
        epilogue<2>(c, nullptr, pred, Bb, Vv, 0, n0, nullptr, nullptr, red,
                    tid, wm, wn, r, q, 0);
    }
}

// ============================================================================
// standalone hf GEMM (pred-hnew)
// ============================================================================
template <int EPI>
__global__ __launch_bounds__(128, 2)
void gemm_hf(const __half* __restrict__ A, const float* __restrict__ Bw,
             const float* __restrict__ bias, float* __restrict__ out,
             int M, int K, int lda, int ldb, int ldc,
             const float* __restrict__ hb, const float* __restrict__ W2) {
    GEMM_PREAMBLE
    const int m0 = blockIdx.y * BM, n0 = blockIdx.x * BN;
    mainloop_hf(A, Bw, K, lda, ldb, m0, n0, c, dynh, tid, wm, wn, aOff, bOff);
    epilogue<EPI>(c, bias, out, M, ldc, m0, n0, hb, W2, red, tid, wm, wn, r, q,
                  blockIdx.x);
}

// ---------------- small kernels ----------------------------------------------
__global__ void k_softmax(const float* __restrict__ part, float* __restrict__ alpha) {
    const int b = blockIdx.x;
    const int s = threadIdx.x; // 128
    float sc = 0.f;
#pragma unroll
    for (int p = 0; p < 8; p++) sc += part[p * (Ss * Bb) + s * Bb + b];
    __shared__ float sh[Ss];
    sh[s] = sc; __syncthreads();
    for (int off = 64; off > 0; off >>= 1) {
        if (s < off) sh[s] = fmaxf(sh[s], sh[s + off]);
        __syncthreads();
    }
    const float mx = sh[0]; __syncthreads();
    const float e = __expf(sc - mx);
    sh[s] = e; __syncthreads();
    for (int off = 64; off > 0; off >>= 1) {
        if (s < off) sh[s] += sh[s + off];
        __syncthreads();
    }
    alpha[s * Bb + b] = e / sh[0];
}

__global__ void k_context(const __half* __restrict__ ench, const float* __restrict__ alpha,
                          __half* __restrict__ xh, __half* __restrict__ c1h) {
    const int b = blockIdx.x;
    const int t = threadIdx.x; // 512
    float a0 = 0.f, a1 = 0.f, a2 = 0.f, a3 = 0.f;
    for (int s = 0; s < Ss; s++) {
        const float al = alpha[s * Bb + b];
        const __half* e = ench + (size_t)(s * Bb + b) * 2048 + t;
        a0 += al * __half2float(e[0]);
        a1 += al * __half2float(e[512]);
        a2 += al * __half2float(e[1024]);
        a3 += al * __half2float(e[1536]);
    }
    const __half h0 = __float2half_rn(a0), h1 = __float2half_rn(a1);
    const __half h2 = __float2half_rn(a2), h3 = __float2half_rn(a3);
    xh[b * 2560 + 512 + t]         = h0;  c1h[b * 3584 + 1024 + t]        = h0;
    xh[b * 2560 + 512 + 512 + t]   = h1;  c1h[b * 3584 + 1024 + 512 + t]  = h1;
    xh[b * 2560 + 512 + 1024 + t]  = h2;  c1h[b * 3584 + 1024 + 1024 + t] = h2;
    xh[b * 2560 + 512 + 1536 + t]  = h3;  c1h[b * 3584 + 1024 + 1536 + t] = h3;
}

__global__ void k_gru(const float* __restrict__ dh, const float* __restrict__ gx,
                      const float* __restrict__ gh, float* __restrict__ hout,
                      __half* __restrict__ c1h) {
    const int b = blockIdx.x;
    const int h = threadIdx.x; // 1024
    const float xr = gx[b * 3072 + h],        hr = gh[b * 3072 + h];
    const float xz = gx[b * 3072 + 1024 + h], hz = gh[b * 3072 + 1024 + h];
    const float xn = gx[b * 3072 + 2048 + h], hn = gh[b * 3072 + 2048 + h];
    const float rg = 1.f / (1.f + __expf(-(xr + hr)));
    const float zg = 1.f / (1.f + __expf(-(xz + hz)));
    const float ng = tanh_fast(xn + rg * hn);
    const float hv = (1.f - zg) * ng + zg * dh[b * Hh + h];
    hout[b * Hh + h] = hv;
    c1h[b * 3584 + h] = __float2half_rn(hv);
}

// ---------------- launch ----------------------------------------------------
extern "C" void kernel_launch(void* const* d_in, const int* in_sizes, int n_in,
                              void* d_out, int out_size) {
    const int*   tl   = (const int*)d_in[0];
    const float* dh   = (const float*)d_in[1];
    const float* enc  = (const float*)d_in[2];
    const float* emb  = (const float*)d_in[3];
    const float* W1   = (const float*)d_in[4];
    const float* b1   = (const float*)d_in[5];
    const float* W2   = (const float*)d_in[6];
    // d_in[7] = b2 (softmax-invariant, skipped)
    const float* Wih  = (const float*)d_in[8];
    const float* Whh  = (const float*)d_in[9];
    const float* bih  = (const float*)d_in[10];
    const float* bhh  = (const float*)d_in[11];
    const float* Wout = (const float*)d_in[12];
    const float* bout = (const float*)d_in[13];

    float* pred = (float*)d_out;                 // [128, 32000]
    float* hout = pred + (size_t)Bb * Vv;        // [128, 1024]

    __half *ench, *w1e, *dhh, *xh, *c1h;
    float *hbp, *part, *alpha, *gx, *gh;
    cudaGetSymbolAddress((void**)&ench,  g_ench);
    cudaGetSymbolAddress((void**)&w1e,   g_w1e);
    cudaGetSymbolAddress((void**)&dhh,   g_dhh);
    cudaGetSymbolAddress((void**)&xh,    g_xh);
    cudaGetSymbolAddress((void**)&c1h,   g_c1h);
    cudaGetSymbolAddress((void**)&hbp,   g_hb);
    cudaGetSymbolAddress((void**)&part,  g_part);
    cudaGetSymbolAddress((void**)&alpha, g_alpha);
    cudaGetSymbolAddress((void**)&gx,    g_gx);
    cudaGetSymbolAddress((void**)&gh,    g_gh);

    cudaFuncSetAttribute(k_prep,    cudaFuncAttributeMaxDynamicSharedMemorySize, DSMEM_BYTES);
    cudaFuncSetAttribute(k_merged1, cudaFuncAttributeMaxDynamicSharedMemorySize, DSMEM_BYTES);
    cudaFuncSetAttribute(k_merged2, cudaFuncAttributeMaxDynamicSharedMemorySize, DSMEM_BYTES);
    cudaFuncSetAttribute(gemm_hf<2>, cudaFuncAttributeMaxDynamicSharedMemorySize, DSMEM_BYTES);

    // 1) prep: all conversions + embeddings + hb GEMM in one launch
    k_prep<<<ENC_B + W1E_B + DH_B + EMB_B + 8, 128, DSMEM_BYTES>>>(
        enc, ench, W1, w1e, dh, dhh, tl, emb, xh, c1h, b1, hbp);

    // 2) merged: energy (1024) + pred-embeds (250, pred = acc + bout) + gh (24)
    k_merged1<<<1298, 128, DSMEM_BYTES>>>(ench, w1e, hbp, W2, part,
                                          c1h, Wout, bout, pred,
                                          dhh, Whh, bhh, gh);

    // 3) softmax over s -> alpha[s][b]
    k_softmax<<<Bb, Ss>>>(part, alpha);

    // 4) context a -> xh[:, 512:], c1h[:, 1024:3072]  (reads fp16 enc)
    k_context<<<Bb, 512>>>(ench, alpha, xh, c1h);

    // 5) merged: gx (24) + pred-a (250, pred += acc) — exactly one wave
    k_merged2<<<274, 128, DSMEM_BYTES>>>(xh, Wih, bih, gx, c1h, Wout, pred);

    // 6) GRU elementwise -> h_new (fp32 tail) and c1h[:, :1024]
    k_gru<<<Bb, Hh>>>(dh, gx, gh, hout, c1h);

    // 7) pred += h_new @ Wout[:, :1024]^T   (K=1024)
    gemm_hf<2><<<dim3(250, 1), 128, DSMEM_BYTES>>>(c1h, Wout, nullptr, pred,
                                                   Bb, Hh, 3584, 3584, Vv,
                                                   nullptr, nullptr);
}

// round 11
// speedup vs baseline: 1.0506x; 1.0506x over previous
#include <cuda_runtime.h>
#include <cuda_fp16.h>
#include <cstdint>

// Problem constants
#define Bb 128
#define Ss 128
#define Hh 1024
#define Ee 512
#define Vv 32000

// fp16 GEMM tile config: CTA 128x128, 4 warps, warp tile 64x64, BK=32, 3 stages
#define BM 128
#define BN 128
#define BK 32
#define SAH 40                       // padded smem row stride in halfs (80B rows)
#define TILE_H (BM * SAH)            // 5120 halfs per A or B tile
#define STAGE_H (2 * TILE_H)         // 10240 halfs per stage
#define NSTG 3
#define DSMEM_BYTES (NSTG * STAGE_H * 2)   // 61440

// ---------------- scratch (device globals; no allocation allowed) ----------
__device__ __align__(256) __half g_ench[(size_t)Ss * Bb * 2 * Hh]; // enc fp16
__device__ __align__(256) __half g_w1e[Hh * 2 * Hh];               // W1[:, :2048] fp16
__device__ __align__(256) __half g_dhh[Bb * Hh];                   // dh fp16
__device__ __align__(256) __half g_xh[Bb * 2560];                  // [embeds | a] fp16
__device__ __align__(256) __half g_c1h[Bb * 3584];                 // [h | a | emb] fp16
__device__ __align__(256) float  g_hb[Bb * Hh];
__device__ __align__(256) float  g_part[8 * Ss * Bb];
__device__ __align__(256) float  g_gx[Bb * 3 * Hh];
__device__ __align__(256) float  g_gh[Bb * 3 * Hh];

// ---------------- helpers ---------------------------------------------------
__device__ __forceinline__ uint32_t smem_u32(const void* p) {
    uint32_t a;
    asm("{ .reg .u64 t; cvta.to.shared.u64 t, %1; cvt.u32.u64 %0, t; }"
        : "=r"(a) : "l"(p));
    return a;
}

__device__ __forceinline__ void mma_f16(float* c,
                                        uint32_t a0, uint32_t a1, uint32_t a2, uint32_t a3,
                                        uint32_t b0, uint32_t b1) {
    asm volatile(
        "mma.sync.aligned.m16n8k16.row.col.f32.f16.f16.f32 "
        "{%0,%1,%2,%3}, {%4,%5,%6,%7}, {%8,%9}, {%0,%1,%2,%3};"
        : "+f"(c[0]), "+f"(c[1]), "+f"(c[2]), "+f"(c[3])
        : "r"(a0), "r"(a1), "r"(a2), "r"(a3), "r"(b0), "r"(b1));
}

__device__ __forceinline__ void ldsm4(uint32_t& r0, uint32_t& r1,
                                      uint32_t& r2, uint32_t& r3, uint32_t addr) {
    asm volatile("ldmatrix.sync.aligned.m8n8.x4.shared.b16 {%0,%1,%2,%3}, [%4];"
                 : "=r"(r0), "=r"(r1), "=r"(r2), "=r"(r3) : "r"(addr));
}

__device__ __forceinline__ void cp16u(uint32_t dst, const void* src) {
    asm volatile("cp.async.ca.shared.global [%0], [%1], 16;" :: "r"(dst), "l"(src));
}
__device__ __forceinline__ void cp_commit() {
    asm volatile("cp.async.commit_group;" ::: "memory");
}
template <int N>
__device__ __forceinline__ void cp_wait() {
    asm volatile("cp.async.wait_group %0;" :: "n"(N) : "memory");
}

__device__ __forceinline__ float tanh_fast(float x) {
    x = fminf(10.f, fmaxf(-10.f, x));
    const float t = __expf(2.f * x);
    return (t - 1.f) / (t + 1.f);
}

__device__ __forceinline__ uint2 cvt_f4_h4(float4 v) {
    half2 h0 = __floats2half2_rn(v.x, v.y);
    half2 h1 = __floats2half2_rn(v.z, v.w);
    uint2 u;
    u.x = *reinterpret_cast<uint32_t*>(&h0);
    u.y = *reinterpret_cast<uint32_t*>(&h1);
    return u;
}

// ---------------- GEMM compute body: ldmatrix + m16n8k16 --------------------
__device__ __forceinline__ void compute_kb(uint32_t aBase, uint32_t bBase,
                                           float c[4][8][4], int wm, int wn,
                                           uint32_t aOff, uint32_t bOff) {
#pragma unroll
    for (int ks = 0; ks < 2; ks++) {
        const uint32_t k0b = ks * 32;   // 16 halfs
        uint32_t af[4][4], bf[4][4];
#pragma unroll
        for (int mf = 0; mf < 4; mf++)
            ldsm4(af[mf][0], af[mf][1], af[mf][2], af[mf][3],
                  aBase + (uint32_t)(((wm * 64 + mf * 16) * SAH) * 2) + k0b + aOff);
#pragma unroll
        for (int np = 0; np < 4; np++)
            ldsm4(bf[np][0], bf[np][1], bf[np][2], bf[np][3],
                  bBase + (uint32_t)(((wn * 64 + np * 16) * SAH) * 2) + k0b + bOff);
#pragma unroll
        for (int nf = 0; nf < 8; nf++) {
            const uint32_t b0 = bf[nf >> 1][(nf & 1) << 1];
            const uint32_t b1 = bf[nf >> 1][((nf & 1) << 1) + 1];
#pragma unroll
            for (int mf = 0; mf < 4; mf++)
                mma_f16(c[mf][nf], af[mf][0], af[mf][1], af[mf][2], af[mf][3], b0, b1);
        }
    }
}

// ---------------- epilogues --------------------------------------------------
// EPI 0: out = acc + bias   EPI 1: energy reduce   EPI 2: out += acc
template <int EPI>
__device__ __forceinline__ void epilogue(float c[4][8][4],
                                         const float* __restrict__ bias,
                                         float* __restrict__ out,
                                         int M, int ldc, int m0, int n0,
                                         const float* __restrict__ hb,
                                         const float* __restrict__ W2,
                                         float (*red)[2],
                                         int tid, int wm, int wn, int r, int q,
                                         int bx) {
    if (EPI == 0 || EPI == 2) {
#pragma unroll
        for (int mf = 0; mf < 4; mf++)
#pragma unroll
            for (int rr = 0; rr < 2; rr++) {
                const int mg = m0 + wm * 64 + mf * 16 + rr * 8 + r;
#pragma unroll
                for (int nf = 0; nf < 8; nf++) {
                    const int ng = n0 + wn * 64 + nf * 8 + q * 2;
                    float* p = &out[(size_t)mg * ldc + ng];
                    float2 v;
                    if (EPI == 0) {
                        v.x = c[mf][nf][rr * 2 + 0] + bias[ng];
                        v.y = c[mf][nf][rr * 2 + 1] + bias[ng + 1];
                    } else {
                        float2 o = *(float2*)p;
                        v.x = o.x + c[mf][nf][rr * 2 + 0];
                        v.y = o.y + c[mf][nf][rr * 2 + 1];
                    }
                    *(float2*)p = v;
                }
            }
    } else {
        float rs[4][2];
#pragma unroll
        for (int mf = 0; mf < 4; mf++)
#pragma unroll
            for (int rr = 0; rr < 2; rr++) {
                const int row = wm * 64 + mf * 16 + rr * 8 + r; // == b
                float acc = 0.f;
#pragma unroll
                for (int nf = 0; nf < 8; nf++) {
                    const int ng = n0 + wn * 64 + nf * 8 + q * 2;
                    const float h0 = hb[row * Hh + ng];
                    const float h1 = hb[row * Hh + ng + 1];
                    acc += tanh_fast(c[mf][nf][rr * 2 + 0] + h0) * W2[ng];
                    acc += tanh_fast(c[mf][nf][rr * 2 + 1] + h1) * W2[ng + 1];
                }
                rs[mf][rr] = acc;
            }
#pragma unroll
        for (int mf = 0; mf < 4; mf++)
#pragma unroll
            for (int rr = 0; rr < 2; rr++) {
                rs[mf][rr] += __shfl_xor_sync(0xffffffffu, rs[mf][rr], 1);
                rs[mf][rr] += __shfl_xor_sync(0xffffffffu, rs[mf][rr], 2);
            }
        if (q == 0) {
#pragma unroll
            for (int mf = 0; mf < 4; mf++)
#pragma unroll
                for (int rr = 0; rr < 2; rr++)
                    red[wm * 64 + mf * 16 + rr * 8 + r][wn] = rs[mf][rr];
        }
        __syncthreads();
        if (tid < BM)
            out[(size_t)bx * M + m0 + tid] = red[tid][0] + red[tid][1];
    }
}

// ---------------- mainloops (device functions, explicit m0/n0) --------------
// HH: A fp16, B fp16 (both cp.async)
__device__ __forceinline__ void mainloop_hh(const __half* __restrict__ A,
                                            const __half* __restrict__ Bw,
                                            int K, int lda, int ldb,
                                            int m0, int n0,
                                            float c[4][8][4], __half* dynh,
                                            int tid, int wm, int wn,
                                            uint32_t aOff, uint32_t bOff) {
    const int nK = K / BK;
    const uint32_t dynU = smem_u32(dynh);
    auto cpfill = [&](int kb, int stg) {
        const uint32_t base = dynU + stg * (STAGE_H * 2);
        const int ko = kb * BK;
#pragma unroll
        for (int h = 0; h < 4; h++) {
            const int cc = tid + h * 128;
            const int row = cc >> 2, g = cc & 3;
            cp16u(base + (row * SAH + g * 8) * 2,
                  A + (size_t)(m0 + row) * lda + ko + g * 8);
            cp16u(base + TILE_H * 2 + (row * SAH + g * 8) * 2,
                  Bw + (size_t)(n0 + row) * ldb + ko + g * 8);
        }
    };
    cpfill(0, 0); cp_commit();
    cpfill(1, 1); cp_commit();
    cp_wait<1>(); __syncthreads();
    int stg = 0;
    for (int kb = 0; kb < nK; kb++) {
        if (kb + 2 < nK) {
            int s2 = stg + 2; if (s2 >= NSTG) s2 -= NSTG;
            cpfill(kb + 2, s2);
        }
        cp_commit();
        const uint32_t aB = dynU + stg * (STAGE_H * 2);
        compute_kb(aB, aB + TILE_H * 2, c, wm, wn, aOff, bOff);
        cp_wait<1>(); __syncthreads();
        if (++stg == NSTG) stg = 0;
    }
}

// HF: A fp16 (cp.async), B fp32 (LDG -> cvt -> STS)
__device__ __forceinline__ void mainloop_hf(const __half* __restrict__ A,
                                            const float* __restrict__ Bw,
                                            int K, int lda, int ldb,
                                            int m0, int n0,
                                            float c[4][8][4], __half* dynh,
                                            int tid, int wm, int wn,
                                            uint32_t aOff, uint32_t bOff) {
    const int nK = K / BK;
    const uint32_t dynU = smem_u32(dynh);
    int rowv[8], gv[8];
#pragma unroll
    for (int h = 0; h < 8; h++) {
        const int idx = tid + h * 128;
        rowv[h] = idx >> 3;
        gv[h]   = idx & 7;
    }
    uint2 sb[8];
    auto cpA = [&](int kb, int stg) {
        const uint32_t base = dynU + stg * (STAGE_H * 2);
        const int ko = kb * BK;
#pragma unroll
        for (int h = 0; h < 4; h++) {
            const int cc = tid + h * 128;
            const int row = cc >> 2, g = cc & 3;
            cp16u(base + (row * SAH + g * 8) * 2,
                  A + (size_t)(m0 + row) * lda + ko + g * 8);
        }
    };
    auto ldB = [&](int kb) {
        const int ko = kb * BK;
#pragma unroll
        for (int h = 0; h < 8; h++)
            sb[h] = cvt_f4_h4(*(const float4*)(Bw + (size_t)(n0 + rowv[h]) * ldb
                                               + ko + gv[h] * 4));
    };
    auto stsB = [&](int stg) {
        __half* D = dynh + stg * STAGE_H + TILE_H;
#pragma unroll
        for (int h = 0; h < 8; h++)
            *(uint2*)(D + rowv[h] * SAH + gv[h] * 4) = sb[h];
    };
    cpA(0, 0); cp_commit();
    cpA(1, 1); cp_commit();
    ldB(0); stsB(0); ldB(1);
    cp_wait<1>(); __syncthreads();
    int stg = 0;
    for (int kb = 0; kb < nK; kb++) {
        int w = stg + 1; if (w == NSTG) w = 0;
        if (kb + 1 < nK) stsB(w);
        if (kb + 2 < nK) {
            int s2 = stg + 2; if (s2 >= NSTG) s2 -= NSTG;
            cpA(kb + 2, s2);
            ldB(kb + 2);
        }
        cp_commit();
        const uint32_t aB = dynU + stg * (STAGE_H * 2);
        compute_kb(aB, aB + TILE_H * 2, c, wm, wn, aOff, bOff);
        cp_wait<1>(); __syncthreads();
        stg = w;
    }
}

// FF: A fp32 and B fp32, both LDG -> cvt -> STS
__device__ __forceinline__ void mainloop_ff(const float* __restrict__ A,
                                            const float* __restrict__ Bw,
                                            int K, int lda, int ldb,
                                            int m0, int n0,
                                            float c[4][8][4], __half* dynh,
                                            int tid, int wm, int wn,
                                            uint32_t aOff, uint32_t bOff) {
    const int nK = K / BK;
    int rowv[8], gv[8];
#pragma unroll
    for (int h = 0; h < 8; h++) {
        const int idx = tid + h * 128;
        rowv[h] = idx >> 3;
        gv[h]   = idx & 7;
    }
    uint2 sa[8], sb[8];
    auto ldAB = [&](int kb) {
        const int ko = kb * BK;
#pragma unroll
        for (int h = 0; h < 8; h++) {
            sa[h] = cvt_f4_h4(*(const float4*)(A  + (size_t)(m0 + rowv[h]) * lda
                                               + ko + gv[h] * 4));
            sb[h] = cvt_f4_h4(*(const float4*)(Bw + (size_t)(n0 + rowv[h]) * ldb
                                               + ko + gv[h] * 4));
        }
    };
    auto stsAB = [&](int stg) {
        __half* D = dynh + stg * STAGE_H;
#pragma unroll
        for (int h = 0; h < 8; h++) {
            *(uint2*)(D + rowv[h] * SAH + gv[h] * 4)          = sa[h];
            *(uint2*)(D + TILE_H + rowv[h] * SAH + gv[h] * 4) = sb[h];
        }
    };
    ldAB(0); stsAB(0);
    if (nK > 1) ldAB(1);
    __syncthreads();
    int stg = 0;
    for (int kb = 0; kb < nK; kb++) {
        int w = stg + 1; if (w == NSTG) w = 0;
        if (kb + 1 < nK) stsAB(w);
        if (kb + 2 < nK) ldAB(kb + 2);
        compute_kb(smem_u32(dynh) + stg * (STAGE_H * 2),
                   smem_u32(dynh) + stg * (STAGE_H * 2) + TILE_H * 2,
                   c, wm, wn, aOff, bOff);
        __syncthreads();
        stg = w;
    }
}

#define GEMM_PREAMBLE \
    extern __shared__ __align__(16) __half dynh[]; \
    __shared__ float red[BM][2]; \
    const int tid = threadIdx.x, lane = tid & 31, wid = tid >> 5; \
    const int wm = wid >> 1, wn = wid & 1, r = lane >> 2, q = lane & 3; \
    const uint32_t aOff = (uint32_t)((((lane & 15) * SAH) + (lane >> 4) * 8) * 2); \
    const uint32_t bOff = (uint32_t)(((((lane >> 4) * 8 + (lane & 7)) * SAH) \
                                      + ((lane >> 3) & 1) * 8) * 2); \
    float c[4][8][4]; \
    _Pragma("unroll") for (int i = 0; i < 4; i++) \
    _Pragma("unroll") for (int j = 0; j < 8; j++) \
    _Pragma("unroll") for (int k = 0; k < 4; k++) c[i][j][k] = 0.f;

// ============================================================================
// k_prep: lightweight (no smem, 256 threads) cvt + embed in one launch
//   [0, 2048)    enc -> fp16    (4096 f4 per block; 8,388,608 f4 total)
//   [2048, 2304) W1[:, :2048] -> fp16 (2048 f4 per block)
//   [2304, 2312) dh -> fp16     (4096 f4 per block)
//   [2312, 2440) embeddings     (one b per block)
// ============================================================================
#define PENC 2048
#define PW1  256
#define PDH  8
#define PEMB 128

__global__ __launch_bounds__(256)
void k_prep(const float* __restrict__ enc, __half* __restrict__ ench,
            const float* __restrict__ W1, __half* __restrict__ w1e,
            const float* __restrict__ dh, __half* __restrict__ dhh,
            const int* __restrict__ tl, const float* __restrict__ emb,
            __half* __restrict__ xh, __half* __restrict__ c1h) {
    const int bid = blockIdx.x;
    const int tid = threadIdx.x;
    if (bid < PENC) {
        const float4* src = (const float4*)enc;
        uint2* dst = (uint2*)ench;
        const int base = bid * 4096 + tid;
#pragma unroll
        for (int j = 0; j < 16; j++)
            dst[base + j * 256] = cvt_f4_h4(src[base + j * 256]);
    } else if (bid < PENC + PW1) {
        const int base = (bid - PENC) * 2048 + tid;
#pragma unroll
        for (int j = 0; j < 8; j++) {
            const int i = base + j * 256;           // f4 index in w1e
            const int row = i >> 9, c4 = i & 511;
            float4 v = *(const float4*)(W1 + (size_t)row * 3072 + c4 * 4);
            *(uint2*)(w1e + row * 2048 + c4 * 4) = cvt_f4_h4(v);
        }
    } else if (bid < PENC + PW1 + PDH) {
        const float4* src = (const float4*)dh;
        uint2* dst = (uint2*)dhh;
        const int base = (bid - PENC - PW1) * 4096 + tid;
#pragma unroll
        for (int j = 0; j < 16; j++)
            dst[base + j * 256] = cvt_f4_h4(src[base + j * 256]);
    } else {
        const int b = bid - PENC - PW1 - PDH;
        const size_t rowoff = (size_t)tl[b] * Ee;
#pragma unroll
        for (int j = 0; j < 2; j++) {
            const int e = tid + j * 256;
            const __half v = __float2half_rn(emb[rowoff + e]);
            xh[b * 2560 + e] = v;
            c1h[b * 3584 + 3072 + e] = v;
        }
    }
}

// ============================================================================
// standalone FF GEMM (hb = dh @ W1h^T + b1; reads fp32 directly)
// ============================================================================
__global__ __launch_bounds__(128, 2)
void gemm_ff_hb(const float* __restrict__ dh, const float* __restrict__ W1h,
                const float* __restrict__ b1, float* __restrict__ hb) {
    GEMM_PREAMBLE
    const int n0 = blockIdx.x * BN;
    mainloop_ff(dh, W1h, Hh, Hh, 3 * Hh, 0, n0, c, dynh, tid, wm, wn, aOff, bOff);
    epilogue<0>(c, b1, hb, Bb, Hh, 0, n0, nullptr, nullptr, red,
                tid, wm, wn, r, q, 0);
}

// ============================================================================
// merged1: [0,1024) energy (hh, EPI1) ; [1024,1274) pred-embeds (hf, EPI0) ;
//          [1274,1298) gh (hf, EPI0)
// ============================================================================
__global__ __launch_bounds__(128, 2)
void k_merged1(const __half* __restrict__ ench, const __half* __restrict__ w1e,
               const float* __restrict__ hb, const float* __restrict__ W2,
               float* __restrict__ part,
               const __half* __restrict__ c1h, const float* __restrict__ Wout,
               const float* __restrict__ bout, float* __restrict__ pred,
               const __half* __restrict__ dhh, const float* __restrict__ Whh,
               const float* __restrict__ bhh, float* __restrict__ gh) {
    GEMM_PREAMBLE
    const int bid = blockIdx.x;
    if (bid < 1024) {
        const int n0 = (bid & 7) * BN, m0 = (bid >> 3) * BM;
        mainloop_hh(ench, w1e, 2 * Hh, 2 * Hh, 2 * Hh, m0, n0,
                    c, dynh, tid, wm, wn, aOff, bOff);
        epilogue<1>(c, nullptr, part, Ss * Bb, 0, m0, n0, hb, W2, red,
                    tid, wm, wn, r, q, bid & 7);
    } else if (bid < 1274) {
        const int n0 = (bid - 1024) * BN;
        mainloop_hf(c1h + 3072, Wout + 3072, Ee, 3584, 3584, 0, n0,
                    c, dynh, tid, wm, wn, aOff, bOff);
        epilogue<0>(c, bout, pred, Bb, Vv, 0, n0, nullptr, nullptr, red,
                    tid, wm, wn, r, q, 0);
    } else {
        const int n0 = (bid - 1274) * BN;
        mainloop_hf(dhh, Whh, Hh, Hh, Hh, 0, n0,
                    c, dynh, tid, wm, wn, aOff, bOff);
        epilogue<0>(c, bhh, gh, Bb, 3 * Hh, 0, n0, nullptr, nullptr, red,
                    tid, wm, wn, r, q, 0);
    }
}

// ============================================================================
// merged2: [0,24) gx ; [24,274) pred-a (EPI2 add) — 274 CTAs = single wave
// ============================================================================
__global__ __launch_bounds__(128, 2)
void k_merged2(const __half* __restrict__ xh, const float* __restrict__ Wih,
               const float* __restrict__ bih, float* __restrict__ gx,
               const __half* __restrict__ c1h, const float* __restrict__ Wout,
               float* __restrict__ pred) {
    GEMM_PREAMBLE
    const int bid = blockIdx.x;
    if (bid < 24) {
        const int n0 = bid * BN;
        mainloop_hf(xh, Wih, 2560, 2560, 2560, 0, n0,
                    c, dynh, tid, wm, wn, aOff, bOff);
        epilogue<0>(c, bih, gx, Bb, 3 * Hh, 0, n0, nullptr, nullptr, red,
                    tid, wm, wn, r, q, 0);
    } else {
        const int n0 = (bid - 24) * BN;
        mainloop_hf(c1h + 1024, Wout + 1024, 2 * Hh, 3584, 3584, 0, n0,
                    c, dynh, tid, wm, wn, aOff, bOff);
        epilogue<2>(c, nullptr, pred, Bb, Vv, 0, n0, nullptr, nullptr, red,
                    tid, wm, wn, r, q, 0);
    }
}

// ============================================================================
// standalone hf GEMM (pred-hnew)
// ============================================================================
template <int EPI>
__global__ __launch_bounds__(128, 2)
void gemm_hf(const __half* __restrict__ A, const float* __restrict__ Bw,
             const float* __restrict__ bias, float* __restrict__ out,
             int M, int K, int lda, int ldb, int ldc,
             const float* __restrict__ hb, const float* __restrict__ W2) {
    GEMM_PREAMBLE
    const int m0 = blockIdx.y * BM, n0 = blockIdx.x * BN;
    mainloop_hf(A, Bw, K, lda, ldb, m0, n0, c, dynh, tid, wm, wn, aOff, bOff);
    epilogue<EPI>(c, bias, out, M, ldc, m0, n0, hb, W2, red, tid, wm, wn, r, q,
                  blockIdx.x);
}

// ============================================================================
// k_ctx: fused softmax + context. One block per b, 1024 threads.
// Phase 1 (tid<128): softmax over s into smem alpha.
// Phase 2: all threads, half2 context accumulation with unroll-8 s-loop.
// ============================================================================
__global__ __launch_bounds__(1024)
void k_ctx(const float* __restrict__ part, const __half* __restrict__ ench,
           __half* __restrict__ xh, __half* __restrict__ c1h) {
    __shared__ float ssc[Ss], sred[Ss], salpha[Ss];
    const int b = blockIdx.x;
    const int tid = threadIdx.x;

    if (tid < Ss) {
        float sc = 0.f;
#pragma unroll
        for (int p = 0; p < 8; p++) sc += part[p * (Ss * Bb) + tid * Bb + b];
        ssc[tid] = sc;
        sred[tid] = sc;
    }
    __syncthreads();
    for (int off = 64; off > 0; off >>= 1) {
        if (tid < off) sred[tid] = fmaxf(sred[tid], sred[tid + off]);
        __syncthreads();
    }
    const float mx = sred[0];
    __syncthreads();
    if (tid < Ss) {
        const float e = __expf(ssc[tid] - mx);
        salpha[tid] = e;
        sred[tid] = e;
    }
    __syncthreads();
    for (int off = 64; off > 0; off >>= 1) {
        if (tid < off) sred[tid] += sred[tid + off];
        __syncthreads();
    }
    const float inv = 1.f / sred[0];
    __syncthreads();
    if (tid < Ss) salpha[tid] *= inv;
    __syncthreads();

    // Phase 2: context. thread tid handles half2 column tid (0..1023).
    const __half2* base = (const __half2*)ench + (size_t)b * 1024 + tid;
    float ax = 0.f, ay = 0.f;
#pragma unroll 8
    for (int s = 0; s < Ss; s++) {
        const float al = salpha[s];
        const float2 v = __half22float2(base[(size_t)s * (Bb * 1024)]);
        ax += al * v.x;
        ay += al * v.y;
    }
    const __half2 hv = __floats2half2_rn(ax, ay);
    *((__half2*)xh  + b * 1280 + 256 + tid) = hv;   // xh[b][512 + 2*tid]
    *((__half2*)c1h + b * 1792 + 512 + tid) = hv;   // c1h[b][1024 + 2*tid]
}

__global__ void k_gru(const float* __restrict__ dh, const float* __restrict__ gx,
                      const float* __restrict__ gh, float* __restrict__ hout,
                      __half* __restrict__ c1h) {
    const int b = blockIdx.x;
    const int h = threadIdx.x; // 1024
    const float xr = gx[b * 3072 + h],        hr = gh[b * 3072 + h];
    const float xz = gx[b * 3072 + 1024 + h], hz = gh[b * 3072 + 1024 + h];
    const float xn = gx[b * 3072 + 2048 + h], hn = gh[b * 3072 + 2048 + h];
    const float rg = 1.f / (1.f + __expf(-(xr + hr)));
    const float zg = 1.f / (1.f + __expf(-(xz + hz)));
    const float ng = tanh_fast(xn + rg * hn);
    const float hv = (1.f - zg) * ng + zg * dh[b * Hh + h];
    hout[b * Hh + h] = hv;
    c1h[b * 3584 + h] = __float2half_rn(hv);
}

// ---------------- launch ----------------------------------------------------
extern "C" void kernel_launch(void* const* d_in, const int* in_sizes, int n_in,
                              void* d_out, int out_size) {
    const int*   tl   = (const int*)d_in[0];
    const float* dh   = (const float*)d_in[1];
    const float* enc  = (const float*)d_in[2];
    const float* emb  = (const float*)d_in[3];
    const float* W1   = (const float*)d_in[4];
    const float* b1   = (const float*)d_in[5];
    const float* W2   = (const float*)d_in[6];
    // d_in[7] = b2 (softmax-invariant, skipped)
    const float* Wih  = (const float*)d_in[8];
    const float* Whh  = (const float*)d_in[9];
    const float* bih  = (const float*)d_in[10];
    const float* bhh  = (const float*)d_in[11];
    const float* Wout = (const float*)d_in[12];
    const float* bout = (const float*)d_in[13];

    float* pred = (float*)d_out;                 // [128, 32000]
    float* hout = pred + (size_t)Bb * Vv;        // [128, 1024]

    __half *ench, *w1e, *dhh, *xh, *c1h;
    float *hbp, *part, *gx, *gh;
    cudaGetSymbolAddress((void**)&ench,  g_ench);
    cudaGetSymbolAddress((void**)&w1e,   g_w1e);
    cudaGetSymbolAddress((void**)&dhh,   g_dhh);
    cudaGetSymbolAddress((void**)&xh,    g_xh);
    cudaGetSymbolAddress((void**)&c1h,   g_c1h);
    cudaGetSymbolAddress((void**)&hbp,   g_hb);
    cudaGetSymbolAddress((void**)&part,  g_part);
    cudaGetSymbolAddress((void**)&gx,    g_gx);
    cudaGetSymbolAddress((void**)&gh,    g_gh);

    cudaFuncSetAttribute(gemm_ff_hb, cudaFuncAttributeMaxDynamicSharedMemorySize, DSMEM_BYTES);
    cudaFuncSetAttribute(k_merged1,  cudaFuncAttributeMaxDynamicSharedMemorySize, DSMEM_BYTES);
    cudaFuncSetAttribute(k_merged2,  cudaFuncAttributeMaxDynamicSharedMemorySize, DSMEM_BYTES);
    cudaFuncSetAttribute(gemm_hf<2>, cudaFuncAttributeMaxDynamicSharedMemorySize, DSMEM_BYTES);

    // 1) prep: conversions + embeddings (no smem, full occupancy)
    k_prep<<<PENC + PW1 + PDH + PEMB, 256>>>(enc, ench, W1, w1e, dh, dhh,
                                             tl, emb, xh, c1h);

    // 2) hb = dh @ W1[:, 2048:3072]^T + b1  (FF: reads fp32 directly)
    gemm_ff_hb<<<8, 128, DSMEM_BYTES>>>(dh, W1 + 2048, b1, hbp);

    // 3) merged: energy (1024) + pred-embeds (250, pred = acc + bout) + gh (24)
    k_merged1<<<1298, 128, DSMEM_BYTES>>>(ench, w1e, hbp, W2, part,
                                          c1h, Wout, bout, pred,
                                          dhh, Whh, bhh, gh);

    // 4) fused softmax + context -> xh[:, 512:], c1h[:, 1024:3072]
    k_ctx<<<Bb, 1024>>>(part, ench, xh, c1h);

    // 5) merged: gx (24) + pred-a (250, pred += acc) — exactly one wave
    k_merged2<<<274, 128, DSMEM_BYTES>>>(xh, Wih, bih, gx, c1h, Wout, pred);

    // 6) GRU elementwise -> h_new (fp32 tail) and c1h[:, :1024]
    k_gru<<<Bb, Hh>>>(dh, gx, gh, hout, c1h);

    // 7) pred += h_new @ Wout[:, :1024]^T   (K=1024)
    gemm_hf<2><<<dim3(250, 1), 128, DSMEM_BYTES>>>(c1h, Wout, nullptr, pred,
                                                   Bb, Hh, 3584, 3584, Vv,
                                                   nullptr, nullptr);
}

// round 12
// speedup vs baseline: 1.0719x; 1.0203x over previous
#include <cuda_runtime.h>
#include <cuda_fp16.h>
#include <cstdint>

// Problem constants
#define Bb 128
#define Ss 128
#define Hh 1024
#define Ee 512
#define Vv 32000

// fp16 GEMM tile config: CTA 128x128, 4 warps, warp tile 64x64, BK=32, 3 stages
#define BM 128
#define BN 128
#define BK 32
#define SAH 40                       // padded smem row stride in halfs (80B rows)
#define TILE_H (BM * SAH)            // 5120 halfs per A or B tile
#define STAGE_H (2 * TILE_H)         // 10240 halfs per stage
#define NSTG 3
#define DSMEM_BYTES (NSTG * STAGE_H * 2)   // 61440

// ---------------- scratch (device globals; no allocation allowed) ----------
__device__ __align__(256) __half g_ench[(size_t)Ss * Bb * 2 * Hh]; // enc fp16
__device__ __align__(256) __half g_w1e[Hh * 2 * Hh];               // W1[:, :2048] fp16
__device__ __align__(256) __half g_dhh[Bb * Hh];                   // dh fp16
__device__ __align__(256) __half g_c1h[Bb * 3584];                 // [h | a | emb] fp16
__device__ __align__(256) float  g_hb[Bb * Hh];
__device__ __align__(256) float  g_part[8 * Ss * Bb];
__device__ __align__(256) float  g_gx[Bb * 3 * Hh];
__device__ __align__(256) float  g_gh[Bb * 3 * Hh];

// ---------------- helpers ---------------------------------------------------
__device__ __forceinline__ uint32_t smem_u32(const void* p) {
    uint32_t a;
    asm("{ .reg .u64 t; cvta.to.shared.u64 t, %1; cvt.u32.u64 %0, t; }"
        : "=r"(a) : "l"(p));
    return a;
}

__device__ __forceinline__ void mma_f16(float* c,
                                        uint32_t a0, uint32_t a1, uint32_t a2, uint32_t a3,
                                        uint32_t b0, uint32_t b1) {
    asm volatile(
        "mma.sync.aligned.m16n8k16.row.col.f32.f16.f16.f32 "
        "{%0,%1,%2,%3}, {%4,%5,%6,%7}, {%8,%9}, {%0,%1,%2,%3};"
        : "+f"(c[0]), "+f"(c[1]), "+f"(c[2]), "+f"(c[3])
        : "r"(a0), "r"(a1), "r"(a2), "r"(a3), "r"(b0), "r"(b1));
}

__device__ __forceinline__ void ldsm4(uint32_t& r0, uint32_t& r1,
                                      uint32_t& r2, uint32_t& r3, uint32_t addr) {
    asm volatile("ldmatrix.sync.aligned.m8n8.x4.shared.b16 {%0,%1,%2,%3}, [%4];"
                 : "=r"(r0), "=r"(r1), "=r"(r2), "=r"(r3) : "r"(addr));
}

__device__ __forceinline__ void cp16u(uint32_t dst, const void* src) {
    asm volatile("cp.async.ca.shared.global [%0], [%1], 16;" :: "r"(dst), "l"(src));
}
__device__ __forceinline__ void cp_commit() {
    asm volatile("cp.async.commit_group;" ::: "memory");
}
template <int N>
__device__ __forceinline__ void cp_wait() {
    asm volatile("cp.async.wait_group %0;" :: "n"(N) : "memory");
}

__device__ __forceinline__ float tanh_fast(float x) {
    x = fminf(10.f, fmaxf(-10.f, x));
    const float t = __expf(2.f * x);
    return (t - 1.f) / (t + 1.f);
}

__device__ __forceinline__ uint2 cvt_f4_h4(float4 v) {
    half2 h0 = __floats2half2_rn(v.x, v.y);
    half2 h1 = __floats2half2_rn(v.z, v.w);
    uint2 u;
    u.x = *reinterpret_cast<uint32_t*>(&h0);
    u.y = *reinterpret_cast<uint32_t*>(&h1);
    return u;
}

// ---------------- GEMM compute body: ldmatrix + m16n8k16 --------------------
__device__ __forceinline__ void compute_kb(uint32_t aBase, uint32_t bBase,
                                           float c[4][8][4], int wm, int wn,
                                           uint32_t aOff, uint32_t bOff) {
#pragma unroll
    for (int ks = 0; ks < 2; ks++) {
        const uint32_t k0b = ks * 32;   // 16 halfs
        uint32_t af[4][4], bf[4][4];
#pragma unroll
        for (int mf = 0; mf < 4; mf++)
            ldsm4(af[mf][0], af[mf][1], af[mf][2], af[mf][3],
                  aBase + (uint32_t)(((wm * 64 + mf * 16) * SAH) * 2) + k0b + aOff);
#pragma unroll
        for (int np = 0; np < 4; np++)
            ldsm4(bf[np][0], bf[np][1], bf[np][2], bf[np][3],
                  bBase + (uint32_t)(((wn * 64 + np * 16) * SAH) * 2) + k0b + bOff);
#pragma unroll
        for (int nf = 0; nf < 8; nf++) {
            const uint32_t b0 = bf[nf >> 1][(nf & 1) << 1];
            const uint32_t b1 = bf[nf >> 1][((nf & 1) << 1) + 1];
#pragma unroll
            for (int mf = 0; mf < 4; mf++)
                mma_f16(c[mf][nf], af[mf][0], af[mf][1], af[mf][2], af[mf][3], b0, b1);
        }
    }
}

// ---------------- epilogues --------------------------------------------------
// EPI 0: out = acc + bias   EPI 1: energy reduce   EPI 2: out += acc
template <int EPI>
__device__ __forceinline__ void epilogue(float c[4][8][4],
                                         const float* __restrict__ bias,
                                         float* __restrict__ out,
                                         int M, int ldc, int m0, int n0,
                                         const float* __restrict__ hb,
                                         const float* __restrict__ W2,
                                         float (*red)[2],
                                         int tid, int wm, int wn, int r, int q,
                                         int bx) {
    if (EPI == 0 || EPI == 2) {
#pragma unroll
        for (int mf = 0; mf < 4; mf++)
#pragma unroll
            for (int rr = 0; rr < 2; rr++) {
                const int mg = m0 + wm * 64 + mf * 16 + rr * 8 + r;
#pragma unroll
                for (int nf = 0; nf < 8; nf++) {
                    const int ng = n0 + wn * 64 + nf * 8 + q * 2;
                    float* p = &out[(size_t)mg * ldc + ng];
                    float2 v;
                    if (EPI == 0) {
                        v.x = c[mf][nf][rr * 2 + 0] + bias[ng];
                        v.y = c[mf][nf][rr * 2 + 1] + bias[ng + 1];
                    } else {
                        float2 o = *(float2*)p;
                        v.x = o.x + c[mf][nf][rr * 2 + 0];
                        v.y = o.y + c[mf][nf][rr * 2 + 1];
                    }
                    *(float2*)p = v;
                }
            }
    } else {
        float rs[4][2];
#pragma unroll
        for (int mf = 0; mf < 4; mf++)
#pragma unroll
            for (int rr = 0; rr < 2; rr++) {
                const int row = wm * 64 + mf * 16 + rr * 8 + r; // == b
                float acc = 0.f;
#pragma unroll
                for (int nf = 0; nf < 8; nf++) {
                    const int ng = n0 + wn * 64 + nf * 8 + q * 2;
                    const float h0 = hb[row * Hh + ng];
                    const float h1 = hb[row * Hh + ng + 1];
                    acc += tanh_fast(c[mf][nf][rr * 2 + 0] + h0) * W2[ng];
                    acc += tanh_fast(c[mf][nf][rr * 2 + 1] + h1) * W2[ng + 1];
                }
                rs[mf][rr] = acc;
            }
#pragma unroll
        for (int mf = 0; mf < 4; mf++)
#pragma unroll
            for (int rr = 0; rr < 2; rr++) {
                rs[mf][rr] += __shfl_xor_sync(0xffffffffu, rs[mf][rr], 1);
                rs[mf][rr] += __shfl_xor_sync(0xffffffffu, rs[mf][rr], 2);
            }
        if (q == 0) {
#pragma unroll
            for (int mf = 0; mf < 4; mf++)
#pragma unroll
                for (int rr = 0; rr < 2; rr++)
                    red[wm * 64 + mf * 16 + rr * 8 + r][wn] = rs[mf][rr];
        }
        __syncthreads();
        if (tid < BM)
            out[(size_t)bx * M + m0 + tid] = red[tid][0] + red[tid][1];
    }
}

// ---------------- mainloops (device functions, explicit m0/n0) --------------
// HH: A fp16, B fp16 (both cp.async)
__device__ __forceinline__ void mainloop_hh(const __half* __restrict__ A,
                                            const __half* __restrict__ Bw,
                                            int K, int lda, int ldb,
                                            int m0, int n0,
                                            float c[4][8][4], __half* dynh,
                                            int tid, int wm, int wn,
                                            uint32_t aOff, uint32_t bOff) {
    const int nK = K / BK;
    const uint32_t dynU = smem_u32(dynh);
    auto cpfill = [&](int kb, int stg) {
        const uint32_t base = dynU + stg * (STAGE_H * 2);
        const int ko = kb * BK;
#pragma unroll
        for (int h = 0; h < 4; h++) {
            const int cc = tid + h * 128;
            const int row = cc >> 2, g = cc & 3;
            cp16u(base + (row * SAH + g * 8) * 2,
                  A + (size_t)(m0 + row) * lda + ko + g * 8);
            cp16u(base + TILE_H * 2 + (row * SAH + g * 8) * 2,
                  Bw + (size_t)(n0 + row) * ldb + ko + g * 8);
        }
    };
    cpfill(0, 0); cp_commit();
    cpfill(1, 1); cp_commit();
    cp_wait<1>(); __syncthreads();
    int stg = 0;
    for (int kb = 0; kb < nK; kb++) {
        if (kb + 2 < nK) {
            int s2 = stg + 2; if (s2 >= NSTG) s2 -= NSTG;
            cpfill(kb + 2, s2);
        }
        cp_commit();
        const uint32_t aB = dynU + stg * (STAGE_H * 2);
        compute_kb(aB, aB + TILE_H * 2, c, wm, wn, aOff, bOff);
        cp_wait<1>(); __syncthreads();
        if (++stg == NSTG) stg = 0;
    }
}

// HF: A fp16 (cp.async), B fp32 (LDG -> cvt -> STS)
__device__ __forceinline__ void mainloop_hf(const __half* __restrict__ A,
                                            const float* __restrict__ Bw,
                                            int K, int lda, int ldb,
                                            int m0, int n0,
                                            float c[4][8][4], __half* dynh,
                                            int tid, int wm, int wn,
                                            uint32_t aOff, uint32_t bOff) {
    const int nK = K / BK;
    const uint32_t dynU = smem_u32(dynh);
    int rowv[8], gv[8];
#pragma unroll
    for (int h = 0; h < 8; h++) {
        const int idx = tid + h * 128;
        rowv[h] = idx >> 3;
        gv[h]   = idx & 7;
    }
    uint2 sb[8];
    auto cpA = [&](int kb, int stg) {
        const uint32_t base = dynU + stg * (STAGE_H * 2);
        const int ko = kb * BK;
#pragma unroll
        for (int h = 0; h < 4; h++) {
            const int cc = tid + h * 128;
            const int row = cc >> 2, g = cc & 3;
            cp16u(base + (row * SAH + g * 8) * 2,
                  A + (size_t)(m0 + row) * lda + ko + g * 8);
        }
    };
    auto ldB = [&](int kb) {
        const int ko = kb * BK;
#pragma unroll
        for (int h = 0; h < 8; h++)
            sb[h] = cvt_f4_h4(*(const float4*)(Bw + (size_t)(n0 + rowv[h]) * ldb
                                               + ko + gv[h] * 4));
    };
    auto stsB = [&](int stg) {
        __half* D = dynh + stg * STAGE_H + TILE_H;
#pragma unroll
        for (int h = 0; h < 8; h++)
            *(uint2*)(D + rowv[h] * SAH + gv[h] * 4) = sb[h];
    };
    cpA(0, 0); cp_commit();
    cpA(1, 1); cp_commit();
    ldB(0); stsB(0); ldB(1);
    cp_wait<1>(); __syncthreads();
    int stg = 0;
    for (int kb = 0; kb < nK; kb++) {
        int w = stg + 1; if (w == NSTG) w = 0;
        if (kb + 1 < nK) stsB(w);
        if (kb + 2 < nK) {
            int s2 = stg + 2; if (s2 >= NSTG) s2 -= NSTG;
            cpA(kb + 2, s2);
            ldB(kb + 2);
        }
        cp_commit();
        const uint32_t aB = dynU + stg * (STAGE_H * 2);
        compute_kb(aB, aB + TILE_H * 2, c, wm, wn, aOff, bOff);
        cp_wait<1>(); __syncthreads();
        stg = w;
    }
}

// FF: A fp32 and B fp32, both LDG -> cvt -> STS
__device__ __forceinline__ void mainloop_ff(const float* __restrict__ A,
                                            const float* __restrict__ Bw,
                                            int K, int lda, int ldb,
                                            int m0, int n0,
                                            float c[4][8][4], __half* dynh,
                                            int tid, int wm, int wn,
                                            uint32_t aOff, uint32_t bOff) {
    const int nK = K / BK;
    int rowv[8], gv[8];
#pragma unroll
    for (int h = 0; h < 8; h++) {
        const int idx = tid + h * 128;
        rowv[h] = idx >> 3;
        gv[h]   = idx & 7;
    }
    uint2 sa[8], sb[8];
    auto ldAB = [&](int kb) {
        const int ko = kb * BK;
#pragma unroll
        for (int h = 0; h < 8; h++) {
            sa[h] = cvt_f4_h4(*(const float4*)(A  + (size_t)(m0 + rowv[h]) * lda
                                               + ko + gv[h] * 4));
            sb[h] = cvt_f4_h4(*(const float4*)(Bw + (size_t)(n0 + rowv[h]) * ldb
                                               + ko + gv[h] * 4));
        }
    };
    auto stsAB = [&](int stg) {
        __half* D = dynh + stg * STAGE_H;
#pragma unroll
        for (int h = 0; h < 8; h++) {
            *(uint2*)(D + rowv[h] * SAH + gv[h] * 4)          = sa[h];
            *(uint2*)(D + TILE_H + rowv[h] * SAH + gv[h] * 4) = sb[h];
        }
    };
    ldAB(0); stsAB(0);
    if (nK > 1) ldAB(1);
    __syncthreads();
    int stg = 0;
    for (int kb = 0; kb < nK; kb++) {
        int w = stg + 1; if (w == NSTG) w = 0;
        if (kb + 1 < nK) stsAB(w);
        if (kb + 2 < nK) ldAB(kb + 2);
        compute_kb(smem_u32(dynh) + stg * (STAGE_H * 2),
                   smem_u32(dynh) + stg * (STAGE_H * 2) + TILE_H * 2,
                   c, wm, wn, aOff, bOff);
        __syncthreads();
        stg = w;
    }
}

#define GEMM_PREAMBLE \
    extern __shared__ __align__(16) __half dynh[]; \
    __shared__ float red[BM][2]; \
    const int tid = threadIdx.x, lane = tid & 31, wid = tid >> 5; \
    const int wm = wid >> 1, wn = wid & 1, r = lane >> 2, q = lane & 3; \
    const uint32_t aOff = (uint32_t)((((lane & 15) * SAH) + (lane >> 4) * 8) * 2); \
    const uint32_t bOff = (uint32_t)(((((lane >> 4) * 8 + (lane & 7)) * SAH) \
                                      + ((lane >> 3) & 1) * 8) * 2); \
    float c[4][8][4]; \
    _Pragma("unroll") for (int i = 0; i < 4; i++) \
    _Pragma("unroll") for (int j = 0; j < 8; j++) \
    _Pragma("unroll") for (int k = 0; k < 4; k++) c[i][j][k] = 0.f;

// ============================================================================
// k_prep: lightweight (no smem, 256 threads) cvt + embed in one launch
//   [0, 2048)    enc -> fp16    (4096 f4 per block; 8,388,608 f4 total)
//   [2048, 2304) W1[:, :2048] -> fp16 (2048 f4 per block)
//   [2304, 2312) dh -> fp16     (4096 f4 per block)
//   [2312, 2440) embeddings     (one b per block)
// ============================================================================
#define PENC 2048
#define PW1  256
#define PDH  8
#define PEMB 128

__global__ __launch_bounds__(256)
void k_prep(const float* __restrict__ enc, __half* __restrict__ ench,
            const float* __restrict__ W1, __half* __restrict__ w1e,
            const float* __restrict__ dh, __half* __restrict__ dhh,
            const int* __restrict__ tl, const float* __restrict__ emb,
            __half* __restrict__ c1h) {
    const int bid = blockIdx.x;
    const int tid = threadIdx.x;
    if (bid < PENC) {
        const float4* src = (const float4*)enc;
        uint2* dst = (uint2*)ench;
        const int base = bid * 4096 + tid;
#pragma unroll
        for (int j = 0; j < 16; j++)
            dst[base + j * 256] = cvt_f4_h4(src[base + j * 256]);
    } else if (bid < PENC + PW1) {
        const int base = (bid - PENC) * 2048 + tid;
#pragma unroll
        for (int j = 0; j < 8; j++) {
            const int i = base + j * 256;           // f4 index in w1e
            const int row = i >> 9, c4 = i & 511;
            float4 v = *(const float4*)(W1 + (size_t)row * 3072 + c4 * 4);
            *(uint2*)(w1e + row * 2048 + c4 * 4) = cvt_f4_h4(v);
        }
    } else if (bid < PENC + PW1 + PDH) {
        const float4* src = (const float4*)dh;
        uint2* dst = (uint2*)dhh;
        const int base = (bid - PENC - PW1) * 4096 + tid;
#pragma unroll
        for (int j = 0; j < 16; j++)
            dst[base + j * 256] = cvt_f4_h4(src[base + j * 256]);
    } else {
        const int b = bid - PENC - PW1 - PDH;
        const size_t rowoff = (size_t)tl[b] * Ee;
#pragma unroll
        for (int j = 0; j < 2; j++) {
            const int e = tid + j * 256;
            c1h[b * 3584 + 3072 + e] = __float2half_rn(emb[rowoff + e]);
        }
    }
}

// ============================================================================
// standalone FF GEMM (hb = dh @ W1h^T + b1; reads fp32 directly)
// ============================================================================
__global__ __launch_bounds__(128, 2)
void gemm_ff_hb(const float* __restrict__ dh, const float* __restrict__ W1h,
                const float* __restrict__ b1, float* __restrict__ hb) {
    GEMM_PREAMBLE
    const int n0 = blockIdx.x * BN;
    mainloop_ff(dh, W1h, Hh, Hh, 3 * Hh, 0, n0, c, dynh, tid, wm, wn, aOff, bOff);
    epilogue<0>(c, b1, hb, Bb, Hh, 0, n0, nullptr, nullptr, red,
                tid, wm, wn, r, q, 0);
}

// ============================================================================
// merged1: [0,1024) energy (hh, EPI1) ; [1024,1274) pred-embeds (hf, EPI0) ;
//          [1274,1298) gh (hf, EPI0)  ; [1298,1322) gx-embeds (hf, EPI0)
// ============================================================================
__global__ __launch_bounds__(128, 2)
void k_merged1(const __half* __restrict__ ench, const __half* __restrict__ w1e,
               const float* __restrict__ hb, const float* __restrict__ W2,
               float* __restrict__ part,
               const __half* __restrict__ c1h, const float* __restrict__ Wout,
               const float* __restrict__ bout, float* __restrict__ pred,
               const __half* __restrict__ dhh, const float* __restrict__ Whh,
               const float* __restrict__ bhh, float* __restrict__ gh,
               const float* __restrict__ Wih, const float* __restrict__ bih,
               float* __restrict__ gx) {
    GEMM_PREAMBLE
    const int bid = blockIdx.x;
    if (bid < 1024) {
        const int n0 = (bid & 7) * BN, m0 = (bid >> 3) * BM;
        mainloop_hh(ench, w1e, 2 * Hh, 2 * Hh, 2 * Hh, m0, n0,
                    c, dynh, tid, wm, wn, aOff, bOff);
        epilogue<1>(c, nullptr, part, Ss * Bb, 0, m0, n0, hb, W2, red,
                    tid, wm, wn, r, q, bid & 7);
    } else if (bid < 1274) {
        const int n0 = (bid - 1024) * BN;
        mainloop_hf(c1h + 3072, Wout + 3072, Ee, 3584, 3584, 0, n0,
                    c, dynh, tid, wm, wn, aOff, bOff);
        epilogue<0>(c, bout, pred, Bb, Vv, 0, n0, nullptr, nullptr, red,
                    tid, wm, wn, r, q, 0);
    } else if (bid < 1298) {
        const int n0 = (bid - 1274) * BN;
        mainloop_hf(dhh, Whh, Hh, Hh, Hh, 0, n0,
                    c, dynh, tid, wm, wn, aOff, bOff);
        epilogue<0>(c, bhh, gh, Bb, 3 * Hh, 0, n0, nullptr, nullptr, red,
                    tid, wm, wn, r, q, 0);
    } else {
        // gx_embeds = embeds @ Wih[:, :512]^T + bih   (K=512)
        const int n0 = (bid - 1298) * BN;
        mainloop_hf(c1h + 3072, Wih, Ee, 3584, 2560, 0, n0,
                    c, dynh, tid, wm, wn, aOff, bOff);
        epilogue<0>(c, bih, gx, Bb, 3 * Hh, 0, n0, nullptr, nullptr, red,
                    tid, wm, wn, r, q, 0);
    }
}

// ============================================================================
// merged2: [0,24) gx-a (K=2048, EPI2) ; [24,274) pred-a (K=2048, EPI2)
//          274 CTAs, uniform 64 kb -> single balanced wave
// ============================================================================
__global__ __launch_bounds__(128, 2)
void k_merged2(const __half* __restrict__ c1h, const float* __restrict__ Wih,
               float* __restrict__ gx,
               const float* __restrict__ Wout, float* __restrict__ pred) {
    GEMM_PREAMBLE
    const int bid = blockIdx.x;
    if (bid < 24) {
        // gx += a @ Wih[:, 512:2560]^T   (a = c1h[:, 1024:3072])
        const int n0 = bid * BN;
        mainloop_hf(c1h + 1024, Wih + 512, 2 * Hh, 3584, 2560, 0, n0,
                    c, dynh, tid, wm, wn, aOff, bOff);
        epilogue<2>(c, nullptr, gx, Bb, 3 * Hh, 0, n0, nullptr, nullptr, red,
                    tid, wm, wn, r, q, 0);
    } else {
        const int n0 = (bid - 24) * BN;
        mainloop_hf(c1h + 1024, Wout + 1024, 2 * Hh, 3584, 3584, 0, n0,
                    c, dynh, tid, wm, wn, aOff, bOff);
        epilogue<2>(c, nullptr, pred, Bb, Vv, 0, n0, nullptr, nullptr, red,
                    tid, wm, wn, r, q, 0);
    }
}

// ============================================================================
// standalone hf GEMM (pred-hnew)
// ============================================================================
template <int EPI>
__global__ __launch_bounds__(128, 2)
void gemm_hf(const __half* __restrict__ A, const float* __restrict__ Bw,
             const float* __restrict__ bias, float* __restrict__ out,
             int M, int K, int lda, int ldb, int ldc,
             const float* __restrict__ hb, const float* __restrict__ W2) {
    GEMM_PREAMBLE
    const int m0 = blockIdx.y * BM, n0 = blockIdx.x * BN;
    mainloop_hf(A, Bw, K, lda, ldb, m0, n0, c, dynh, tid, wm, wn, aOff, bOff);
    epilogue<EPI>(c, bias, out, M, ldc, m0, n0, hb, W2, red, tid, wm, wn, r, q,
                  blockIdx.x);
}

// ============================================================================
// k_ctx: fused softmax + context. 256 blocks (2 per b), 512 threads.
// Block (b, half): softmax over s (tid<128), then 512 half2 columns
// [half*512, half*512+512).
// ============================================================================
__global__ __launch_bounds__(512)
void k_ctx(const float* __restrict__ part, const __half* __restrict__ ench,
           __half* __restrict__ c1h) {
    __shared__ float ssc[Ss], sred[Ss], salpha[Ss];
    const int b    = blockIdx.x >> 1;
    const int half = blockIdx.x & 1;
    const int tid  = threadIdx.x;

    if (tid < Ss) {
        float sc = 0.f;
#pragma unroll
        for (int p = 0; p < 8; p++) sc += part[p * (Ss * Bb) + tid * Bb + b];
        ssc[tid] = sc;
        sred[tid] = sc;
    }
    __syncthreads();
    for (int off = 64; off > 0; off >>= 1) {
        if (tid < off) sred[tid] = fmaxf(sred[tid], sred[tid + off]);
        __syncthreads();
    }
    const float mx = sred[0];
    __syncthreads();
    if (tid < Ss) {
        const float e = __expf(ssc[tid] - mx);
        salpha[tid] = e;
        sred[tid] = e;
    }
    __syncthreads();
    for (int off = 64; off > 0; off >>= 1) {
        if (tid < off) sred[tid] += sred[tid + off];
        __syncthreads();
    }
    const float inv = 1.f / sred[0];
    __syncthreads();
    if (tid < Ss) salpha[tid] *= inv;
    __syncthreads();

    // context: half2 column col (0..1023 overall)
    const int col = half * 512 + tid;
    const __half2* base = (const __half2*)ench + (size_t)b * 1024 + col;
    float ax = 0.f, ay = 0.f;
#pragma unroll 8
    for (int s = 0; s < Ss; s++) {
        const float al = salpha[s];
        const float2 v = __half22float2(base[(size_t)s * (Bb * 1024)]);
        ax += al * v.x;
        ay += al * v.y;
    }
    *((__half2*)c1h + b * 1792 + 512 + col) = __floats2half2_rn(ax, ay);
}

__global__ void k_gru(const float* __restrict__ dh, const float* __restrict__ gx,
                      const float* __restrict__ gh, float* __restrict__ hout,
                      __half* __restrict__ c1h) {
    const int b = blockIdx.x;
    const int h = threadIdx.x; // 1024
    const float xr = gx[b * 3072 + h],        hr = gh[b * 3072 + h];
    const float xz = gx[b * 3072 + 1024 + h], hz = gh[b * 3072 + 1024 + h];
    const float xn = gx[b * 3072 + 2048 + h], hn = gh[b * 3072 + 2048 + h];
    const float rg = 1.f / (1.f + __expf(-(xr + hr)));
    const float zg = 1.f / (1.f + __expf(-(xz + hz)));
    const float ng = tanh_fast(xn + rg * hn);
    const float hv = (1.f - zg) * ng + zg * dh[b * Hh + h];
    hout[b * Hh + h] = hv;
    c1h[b * 3584 + h] = __float2half_rn(hv);
}

// ---------------- launch ----------------------------------------------------
extern "C" void kernel_launch(void* const* d_in, const int* in_sizes, int n_in,
                              void* d_out, int out_size) {
    const int*   tl   = (const int*)d_in[0];
    const float* dh   = (const float*)d_in[1];
    const float* enc  = (const float*)d_in[2];
    const float* emb  = (const float*)d_in[3];
    const float* W1   = (const float*)d_in[4];
    const float* b1   = (const float*)d_in[5];
    const float* W2   = (const float*)d_in[6];
    // d_in[7] = b2 (softmax-invariant, skipped)
    const float* Wih  = (const float*)d_in[8];
    const float* Whh  = (const float*)d_in[9];
    const float* bih  = (const float*)d_in[10];
    const float* bhh  = (const float*)d_in[11];
    const float* Wout = (const float*)d_in[12];
    const float* bout = (const float*)d_in[13];

    float* pred = (float*)d_out;                 // [128, 32000]
    float* hout = pred + (size_t)Bb * Vv;        // [128, 1024]

    __half *ench, *w1e, *dhh, *c1h;
    float *hbp, *part, *gx, *gh;
    cudaGetSymbolAddress((void**)&ench,  g_ench);
    cudaGetSymbolAddress((void**)&w1e,   g_w1e);
    cudaGetSymbolAddress((void**)&dhh,   g_dhh);
    cudaGetSymbolAddress((void**)&c1h,   g_c1h);
    cudaGetSymbolAddress((void**)&hbp,   g_hb);
    cudaGetSymbolAddress((void**)&part,  g_part);
    cudaGetSymbolAddress((void**)&gx,    g_gx);
    cudaGetSymbolAddress((void**)&gh,    g_gh);

    cudaFuncSetAttribute(gemm_ff_hb, cudaFuncAttributeMaxDynamicSharedMemorySize, DSMEM_BYTES);
    cudaFuncSetAttribute(k_merged1,  cudaFuncAttributeMaxDynamicSharedMemorySize, DSMEM_BYTES);
    cudaFuncSetAttribute(k_merged2,  cudaFuncAttributeMaxDynamicSharedMemorySize, DSMEM_BYTES);
    cudaFuncSetAttribute(gemm_hf<2>, cudaFuncAttributeMaxDynamicSharedMemorySize, DSMEM_BYTES);

    // 1) prep: conversions + embeddings (no smem, full occupancy)
    k_prep<<<PENC + PW1 + PDH + PEMB, 256>>>(enc, ench, W1, w1e, dh, dhh,
                                             tl, emb, c1h);

    // 2) hb = dh @ W1[:, 2048:3072]^T + b1  (FF: reads fp32 directly)
    gemm_ff_hb<<<8, 128, DSMEM_BYTES>>>(dh, W1 + 2048, b1, hbp);

    // 3) merged: energy (1024) + pred-embeds (250) + gh (24) + gx-embeds (24)
    k_merged1<<<1322, 128, DSMEM_BYTES>>>(ench, w1e, hbp, W2, part,
                                          c1h, Wout, bout, pred,
                                          dhh, Whh, bhh, gh,
                                          Wih, bih, gx);

    // 4) fused softmax + context -> c1h[:, 1024:3072]  (2 blocks per b)
    k_ctx<<<2 * Bb, 512>>>(part, ench, c1h);

    // 5) merged: gx += a-part (24) + pred += a-part (250) — uniform single wave
    k_merged2<<<274, 128, DSMEM_BYTES>>>(c1h, Wih, gx, Wout, pred);

    // 6) GRU elementwise -> h_new (fp32 tail) and c1h[:, :1024]
    k_gru<<<Bb, Hh>>>(dh, gx, gh, hout, c1h);

    // 7) pred += h_new @ Wout[:, :1024]^T   (K=1024)
    gemm_hf<2><<<dim3(250, 1), 128, DSMEM_BYTES>>>(c1h, Wout, nullptr, pred,
                                                   Bb, Hh, 3584, 3584, Vv,
                                                   nullptr, nullptr);
}

// round 13
// speedup vs baseline: 1.1108x; 1.0363x over previous
#include <cuda_runtime.h>
#include <cuda_fp16.h>
#include <cstdint>

// Problem constants
#define Bb 128
#define Ss 128
#define Hh 1024
#define Ee 512
#define Vv 32000

// fp16 GEMM tile config: CTA 128x128, 4 warps, warp tile 64x64, BK=32, 3 stages
#define BM 128
#define BN 128
#define BK 32
#define SAH 40                       // padded smem row stride in halfs (80B rows)
#define TILE_H (BM * SAH)            // 5120 halfs per A or B tile
#define STAGE_H (2 * TILE_H)         // 10240 halfs per stage
#define NSTG 3
#define DSMEM_BYTES (NSTG * STAGE_H * 2)   // 61440

// ---------------- scratch (device globals; no allocation allowed) ----------
__device__ __align__(256) __half g_ench[(size_t)Ss * Bb * 2 * Hh]; // enc fp16
__device__ __align__(256) __half g_w1e[Hh * 2 * Hh];               // W1[:, :2048] fp16
__device__ __align__(256) __half g_dhh[Bb * Hh];                   // dh fp16
__device__ __align__(256) __half g_c1h[Bb * 3584];                 // [h | a | emb] fp16
__device__ __align__(256) float  g_hb[Bb * Hh];
__device__ __align__(256) float  g_part[8 * Ss * Bb];
__device__ __align__(256) float  g_gx[Bb * 3 * Hh];
__device__ __align__(256) float  g_gh[Bb * 3 * Hh];
__device__ int g_hb_flag;    // counts hb producer CTAs (target 8)
__device__ int g_gru_flag;   // counts gru producer CTAs (target 128)

// ---------------- helpers ---------------------------------------------------
__device__ __forceinline__ uint32_t smem_u32(const void* p) {
    uint32_t a;
    asm("{ .reg .u64 t; cvta.to.shared.u64 t, %1; cvt.u32.u64 %0, t; }"
        : "=r"(a) : "l"(p));
    return a;
}

__device__ __forceinline__ void mma_f16(float* c,
                                        uint32_t a0, uint32_t a1, uint32_t a2, uint32_t a3,
                                        uint32_t b0, uint32_t b1) {
    asm volatile(
        "mma.sync.aligned.m16n8k16.row.col.f32.f16.f16.f32 "
        "{%0,%1,%2,%3}, {%4,%5,%6,%7}, {%8,%9}, {%0,%1,%2,%3};"
        : "+f"(c[0]), "+f"(c[1]), "+f"(c[2]), "+f"(c[3])
        : "r"(a0), "r"(a1), "r"(a2), "r"(a3), "r"(b0), "r"(b1));
}

__device__ __forceinline__ void ldsm4(uint32_t& r0, uint32_t& r1,
                                      uint32_t& r2, uint32_t& r3, uint32_t addr) {
    asm volatile("ldmatrix.sync.aligned.m8n8.x4.shared.b16 {%0,%1,%2,%3}, [%4];"
                 : "=r"(r0), "=r"(r1), "=r"(r2), "=r"(r3) : "r"(addr));
}

__device__ __forceinline__ void cp16u(uint32_t dst, const void* src) {
    asm volatile("cp.async.ca.shared.global [%0], [%1], 16;" :: "r"(dst), "l"(src));
}
__device__ __forceinline__ void cp_commit() {
    asm volatile("cp.async.commit_group;" ::: "memory");
}
template <int N>
__device__ __forceinline__ void cp_wait() {
    asm volatile("cp.async.wait_group %0;" :: "n"(N) : "memory");
}

__device__ __forceinline__ float tanh_fast(float x) {
    x = fminf(10.f, fmaxf(-10.f, x));
    const float t = __expf(2.f * x);
    return (t - 1.f) / (t + 1.f);
}

__device__ __forceinline__ uint2 cvt_f4_h4(float4 v) {
    half2 h0 = __floats2half2_rn(v.x, v.y);
    half2 h1 = __floats2half2_rn(v.z, v.w);
    uint2 u;
    u.x = *reinterpret_cast<uint32_t*>(&h0);
    u.y = *reinterpret_cast<uint32_t*>(&h1);
    return u;
}

// producer arrive: all threads fence own writes, sync, one thread bumps flag
__device__ __forceinline__ void flag_arrive(int* flag) {
    __threadfence();
    __syncthreads();
    if (threadIdx.x == 0) atomicAdd(flag, 1);
}
// consumer wait: spin until flag reaches target, then fence for acquire
__device__ __forceinline__ void flag_wait(int* flag, int target) {
    if (threadIdx.x == 0) {
        while (*(volatile int*)flag < target) {}
    }
    __syncthreads();
    __threadfence();
}

// ---------------- GEMM compute body: ldmatrix + m16n8k16 --------------------
__device__ __forceinline__ void compute_kb(uint32_t aBase, uint32_t bBase,
                                           float c[4][8][4], int wm, int wn,
                                           uint32_t aOff, uint32_t bOff) {
#pragma unroll
    for (int ks = 0; ks < 2; ks++) {
        const uint32_t k0b = ks * 32;   // 16 halfs
        uint32_t af[4][4], bf[4][4];
#pragma unroll
        for (int mf = 0; mf < 4; mf++)
            ldsm4(af[mf][0], af[mf][1], af[mf][2], af[mf][3],
                  aBase + (uint32_t)(((wm * 64 + mf * 16) * SAH) * 2) + k0b + aOff);
#pragma unroll
        for (int np = 0; np < 4; np++)
            ldsm4(bf[np][0], bf[np][1], bf[np][2], bf[np][3],
                  bBase + (uint32_t)(((wn * 64 + np * 16) * SAH) * 2) + k0b + bOff);
#pragma unroll
        for (int nf = 0; nf < 8; nf++) {
            const uint32_t b0 = bf[nf >> 1][(nf & 1) << 1];
            const uint32_t b1 = bf[nf >> 1][((nf & 1) << 1) + 1];
#pragma unroll
            for (int mf = 0; mf < 4; mf++)
                mma_f16(c[mf][nf], af[mf][0], af[mf][1], af[mf][2], af[mf][3], b0, b1);
        }
    }
}

// ---------------- epilogues --------------------------------------------------
// EPI 0: out = acc + bias   EPI 1: energy reduce   EPI 2: out += acc
template <int EPI>
__device__ __forceinline__ void epilogue(float c[4][8][4],
                                         const float* __restrict__ bias,
                                         float* __restrict__ out,
                                         int M, int ldc, int m0, int n0,
                                         const float* __restrict__ hb,
                                         const float* __restrict__ W2,
                                         float (*red)[2],
                                         int tid, int wm, int wn, int r, int q,
                                         int bx) {
    if (EPI == 0 || EPI == 2) {
#pragma unroll
        for (int mf = 0; mf < 4; mf++)
#pragma unroll
            for (int rr = 0; rr < 2; rr++) {
                const int mg = m0 + wm * 64 + mf * 16 + rr * 8 + r;
#pragma unroll
                for (int nf = 0; nf < 8; nf++) {
                    const int ng = n0 + wn * 64 + nf * 8 + q * 2;
                    float* p = &out[(size_t)mg * ldc + ng];
                    float2 v;
                    if (EPI == 0) {
                        v.x = c[mf][nf][rr * 2 + 0] + bias[ng];
                        v.y = c[mf][nf][rr * 2 + 1] + bias[ng + 1];
                    } else {
                        float2 o = *(float2*)p;
                        v.x = o.x + c[mf][nf][rr * 2 + 0];
                        v.y = o.y + c[mf][nf][rr * 2 + 1];
                    }
                    *(float2*)p = v;
                }
            }
    } else {
        float rs[4][2];
#pragma unroll
        for (int mf = 0; mf < 4; mf++)
#pragma unroll
            for (int rr = 0; rr < 2; rr++) {
                const int row = wm * 64 + mf * 16 + rr * 8 + r; // == b
                float acc = 0.f;
#pragma unroll
                for (int nf = 0; nf < 8; nf++) {
                    const int ng = n0 + wn * 64 + nf * 8 + q * 2;
                    const float h0 = hb[row * Hh + ng];
                    const float h1 = hb[row * Hh + ng + 1];
                    acc += tanh_fast(c[mf][nf][rr * 2 + 0] + h0) * W2[ng];
                    acc += tanh_fast(c[mf][nf][rr * 2 + 1] + h1) * W2[ng + 1];
                }
                rs[mf][rr] = acc;
            }
#pragma unroll
        for (int mf = 0; mf < 4; mf++)
#pragma unroll
            for (int rr = 0; rr < 2; rr++) {
                rs[mf][rr] += __shfl_xor_sync(0xffffffffu, rs[mf][rr], 1);
                rs[mf][rr] += __shfl_xor_sync(0xffffffffu, rs[mf][rr], 2);
            }
        if (q == 0) {
#pragma unroll
            for (int mf = 0; mf < 4; mf++)
#pragma unroll
                for (int rr = 0; rr < 2; rr++)
                    red[wm * 64 + mf * 16 + rr * 8 + r][wn] = rs[mf][rr];
        }
        __syncthreads();
        if (tid < BM)
            out[(size_t)bx * M + m0 + tid] = red[tid][0] + red[tid][1];
    }
}

// ---------------- mainloops (device functions, explicit m0/n0) --------------
// HH: A fp16, B fp16 (both cp.async)
__device__ __forceinline__ void mainloop_hh(const __half* __restrict__ A,
                                            const __half* __restrict__ Bw,
                                            int K, int lda, int ldb,
                                            int m0, int n0,
                                            float c[4][8][4], __half* dynh,
                                            int tid, int wm, int wn,
                                            uint32_t aOff, uint32_t bOff) {
    const int nK = K / BK;
    const uint32_t dynU = smem_u32(dynh);
    auto cpfill = [&](int kb, int stg) {
        const uint32_t base = dynU + stg * (STAGE_H * 2);
        const int ko = kb * BK;
#pragma unroll
        for (int h = 0; h < 4; h++) {
            const int cc = tid + h * 128;
            const int row = cc >> 2, g = cc & 3;
            cp16u(base + (row * SAH + g * 8) * 2,
                  A + (size_t)(m0 + row) * lda + ko + g * 8);
            cp16u(base + TILE_H * 2 + (row * SAH + g * 8) * 2,
                  Bw + (size_t)(n0 + row) * ldb + ko + g * 8);
        }
    };
    cpfill(0, 0); cp_commit();
    cpfill(1, 1); cp_commit();
    cp_wait<1>(); __syncthreads();
    int stg = 0;
    for (int kb = 0; kb < nK; kb++) {
        if (kb + 2 < nK) {
            int s2 = stg + 2; if (s2 >= NSTG) s2 -= NSTG;
            cpfill(kb + 2, s2);
        }
        cp_commit();
        const uint32_t aB = dynU + stg * (STAGE_H * 2);
        compute_kb(aB, aB + TILE_H * 2, c, wm, wn, aOff, bOff);
        cp_wait<1>(); __syncthreads();
        if (++stg == NSTG) stg = 0;
    }
}

// HF: A fp16 (cp.async), B fp32 (LDG -> cvt -> STS)
__device__ __forceinline__ void mainloop_hf(const __half* __restrict__ A,
                                            const float* __restrict__ Bw,
                                            int K, int lda, int ldb,
                                            int m0, int n0,
                                            float c[4][8][4], __half* dynh,
                                            int tid, int wm, int wn,
                                            uint32_t aOff, uint32_t bOff) {
    const int nK = K / BK;
    const uint32_t dynU = smem_u32(dynh);
    int rowv[8], gv[8];
#pragma unroll
    for (int h = 0; h < 8; h++) {
        const int idx = tid + h * 128;
        rowv[h] = idx >> 3;
        gv[h]   = idx & 7;
    }
    uint2 sb[8];
    auto cpA = [&](int kb, int stg) {
        const uint32_t base = dynU + stg * (STAGE_H * 2);
        const int ko = kb * BK;
#pragma unroll
        for (int h = 0; h < 4; h++) {
            const int cc = tid + h * 128;
            const int row = cc >> 2, g = cc & 3;
            cp16u(base + (row * SAH + g * 8) * 2,
                  A + (size_t)(m0 + row) * lda + ko + g * 8);
        }
    };
    auto ldB = [&](int kb) {
        const int ko = kb * BK;
#pragma unroll
        for (int h = 0; h < 8; h++)
            sb[h] = cvt_f4_h4(*(const float4*)(Bw + (size_t)(n0 + rowv[h]) * ldb
                                               + ko + gv[h] * 4));
    };
    auto stsB = [&](int stg) {
        __half* D = dynh + stg * STAGE_H + TILE_H;
#pragma unroll
        for (int h = 0; h < 8; h++)
            *(uint2*)(D + rowv[h] * SAH + gv[h] * 4) = sb[h];
    };
    cpA(0, 0); cp_commit();
    cpA(1, 1); cp_commit();
    ldB(0); stsB(0); ldB(1);
    cp_wait<1>(); __syncthreads();
    int stg = 0;
    for (int kb = 0; kb < nK; kb++) {
        int w = stg + 1; if (w == NSTG) w = 0;
        if (kb + 1 < nK) stsB(w);
        if (kb + 2 < nK) {
            int s2 = stg + 2; if (s2 >= NSTG) s2 -= NSTG;
            cpA(kb + 2, s2);
            ldB(kb + 2);
        }
        cp_commit();
        const uint32_t aB = dynU + stg * (STAGE_H * 2);
        compute_kb(aB, aB + TILE_H * 2, c, wm, wn, aOff, bOff);
        cp_wait<1>(); __syncthreads();
        stg = w;
    }
}

// FF: A fp32 and B fp32, both LDG -> cvt -> STS
__device__ __forceinline__ void mainloop_ff(const float* __restrict__ A,
                                            const float* __restrict__ Bw,
                                            int K, int lda, int ldb,
                                            int m0, int n0,
                                            float c[4][8][4], __half* dynh,
                                            int tid, int wm, int wn,
                                            uint32_t aOff, uint32_t bOff) {
    const int nK = K / BK;
    int rowv[8], gv[8];
#pragma unroll
    for (int h = 0; h < 8; h++) {
        const int idx = tid + h * 128;
        rowv[h] = idx >> 3;
        gv[h]   = idx & 7;
    }
    uint2 sa[8], sb[8];
    auto ldAB = [&](int kb) {
        const int ko = kb * BK;
#pragma unroll
        for (int h = 0; h < 8; h++) {
            sa[h] = cvt_f4_h4(*(const float4*)(A  + (size_t)(m0 + rowv[h]) * lda
                                               + ko + gv[h] * 4));
            sb[h] = cvt_f4_h4(*(const float4*)(Bw + (size_t)(n0 + rowv[h]) * ldb
                                               + ko + gv[h] * 4));
        }
    };
    auto stsAB = [&](int stg) {
        __half* D = dynh + stg * STAGE_H;
#pragma unroll
        for (int h = 0; h < 8; h++) {
            *(uint2*)(D + rowv[h] * SAH + gv[h] * 4)          = sa[h];
            *(uint2*)(D + TILE_H + rowv[h] * SAH + gv[h] * 4) = sb[h];
        }
    };
    ldAB(0); stsAB(0);
    if (nK > 1) ldAB(1);
    __syncthreads();
    int stg = 0;
    for (int kb = 0; kb < nK; kb++) {
        int w = stg + 1; if (w == NSTG) w = 0;
        if (kb + 1 < nK) stsAB(w);
        if (kb + 2 < nK) ldAB(kb + 2);
        compute_kb(smem_u32(dynh) + stg * (STAGE_H * 2),
                   smem_u32(dynh) + stg * (STAGE_H * 2) + TILE_H * 2,
                   c, wm, wn, aOff, bOff);
        __syncthreads();
        stg = w;
    }
}

#define GEMM_PREAMBLE \
    extern __shared__ __align__(16) __half dynh[]; \
    __shared__ float red[BM][2]; \
    const int tid = threadIdx.x, lane = tid & 31, wid = tid >> 5; \
    const int wm = wid >> 1, wn = wid & 1, r = lane >> 2, q = lane & 3; \
    const uint32_t aOff = (uint32_t)((((lane & 15) * SAH) + (lane >> 4) * 8) * 2); \
    const uint32_t bOff = (uint32_t)(((((lane >> 4) * 8 + (lane & 7)) * SAH) \
                                      + ((lane >> 3) & 1) * 8) * 2); \
    float c[4][8][4]; \
    _Pragma("unroll") for (int i = 0; i < 4; i++) \
    _Pragma("unroll") for (int j = 0; j < 8; j++) \
    _Pragma("unroll") for (int k = 0; k < 4; k++) c[i][j][k] = 0.f;

// ============================================================================
// k_prep: lightweight (no smem, 256 threads) cvt + embed in one launch
//   [0, 2048)    enc -> fp16    (4096 f4 per block; 8,388,608 f4 total)
//   [2048, 2304) W1[:, :2048] -> fp16 (2048 f4 per block)
//   [2304, 2312) dh -> fp16     (4096 f4 per block)
//   [2312, 2440) embeddings     (one b per block)
//   block 0 thread 0 also resets the producer flags for this replay.
// ============================================================================
#define PENC 2048
#define PW1  256
#define PDH  8
#define PEMB 128

__global__ __launch_bounds__(256)
void k_prep(const float* __restrict__ enc, __half* __restrict__ ench,
            const float* __restrict__ W1, __half* __restrict__ w1e,
            const float* __restrict__ dh, __half* __restrict__ dhh,
            const int* __restrict__ tl, const float* __restrict__ emb,
            __half* __restrict__ c1h) {
    const int bid = blockIdx.x;
    const int tid = threadIdx.x;
    if (bid == 0 && tid == 0) { g_hb_flag = 0; g_gru_flag = 0; }
    if (bid < PENC) {
        const float4* src = (const float4*)enc;
        uint2* dst = (uint2*)ench;
        const int base = bid * 4096 + tid;
#pragma unroll
        for (int j = 0; j < 16; j++)
            dst[base + j * 256] = cvt_f4_h4(src[base + j * 256]);
    } else if (bid < PENC + PW1) {
        const int base = (bid - PENC) * 2048 + tid;
#pragma unroll
        for (int j = 0; j < 8; j++) {
            const int i = base + j * 256;           // f4 index in w1e
            const int row = i >> 9, c4 = i & 511;
            float4 v = *(const float4*)(W1 + (size_t)row * 3072 + c4 * 4);
            *(uint2*)(w1e + row * 2048 + c4 * 4) = cvt_f4_h4(v);
        }
    } else if (bid < PENC + PW1 + PDH) {
        const float4* src = (const float4*)dh;
        uint2* dst = (uint2*)dhh;
        const int base = (bid - PENC - PW1) * 4096 + tid;
#pragma unroll
        for (int j = 0; j < 16; j++)
            dst[base + j * 256] = cvt_f4_h4(src[base + j * 256]);
    } else {
        const int b = bid - PENC - PW1 - PDH;
        const size_t rowoff = (size_t)tl[b] * Ee;
#pragma unroll
        for (int j = 0; j < 2; j++) {
            const int e = tid + j * 256;
            c1h[b * 3584 + 3072 + e] = __float2half_rn(emb[rowoff + e]);
        }
    }
}

// ============================================================================
// merged1: [0,8) hb (ff, EPI0, arrives g_hb_flag) ;
//          [8,1032) energy (hh, EPI1, waits g_hb_flag==8) ;
//          [1032,1282) pred-embeds (hf, EPI0) ;
//          [1282,1306) gh (hf, EPI0) ; [1306,1330) gx-embeds (hf, EPI0)
// ============================================================================
__global__ __launch_bounds__(128, 2)
void k_merged1(const __half* __restrict__ ench, const __half* __restrict__ w1e,
               const float* __restrict__ dh, const float* __restrict__ W1,
               const float* __restrict__ b1, float* __restrict__ hbp,
               const float* __restrict__ W2, float* __restrict__ part,
               const __half* __restrict__ c1h, const float* __restrict__ Wout,
               const float* __restrict__ bout, float* __restrict__ pred,
               const __half* __restrict__ dhh, const float* __restrict__ Whh,
               const float* __restrict__ bhh, float* __restrict__ gh,
               const float* __restrict__ Wih, const float* __restrict__ bih,
               float* __restrict__ gx) {
    GEMM_PREAMBLE
    const int bid = blockIdx.x;
    if (bid < 8) {
        // hb = dh @ W1[:, 2048:3072]^T + b1  (fp32 inputs, K=1024)
        const int n0 = bid * BN;
        mainloop_ff(dh, W1 + 2048, Hh, Hh, 3 * Hh, 0, n0,
                    c, dynh, tid, wm, wn, aOff, bOff);
        epilogue<0>(c, b1, hbp, Bb, Hh, 0, n0, nullptr, nullptr, red,
                    tid, wm, wn, r, q, 0);
        flag_arrive(&g_hb_flag);
    } else if (bid < 1032) {
        const int idx = bid - 8;
        const int n0 = (idx & 7) * BN, m0 = (idx >> 3) * BM;
        mainloop_hh(ench, w1e, 2 * Hh, 2 * Hh, 2 * Hh, m0, n0,
                    c, dynh, tid, wm, wn, aOff, bOff);
        flag_wait(&g_hb_flag, 8);   // hb ready long before any epilogue
        epilogue<1>(c, nullptr, part, Ss * Bb, 0, m0, n0, hbp, W2, red,
                    tid, wm, wn, r, q, idx & 7);
    } else if (bid < 1282) {
        const int n0 = (bid - 1032) * BN;
        mainloop_hf(c1h + 3072, Wout + 3072, Ee, 3584, 3584, 0, n0,
                    c, dynh, tid, wm, wn, aOff, bOff);
        epilogue<0>(c, bout, pred, Bb, Vv, 0, n0, nullptr, nullptr, red,
                    tid, wm, wn, r, q, 0);
    } else if (bid < 1306) {
        const int n0 = (bid - 1282) * BN;
        mainloop_hf(dhh, Whh, Hh, Hh, Hh, 0, n0,
                    c, dynh, tid, wm, wn, aOff, bOff);
        epilogue<0>(c, bhh, gh, Bb, 3 * Hh, 0, n0, nullptr, nullptr, red,
                    tid, wm, wn, r, q, 0);
    } else {
        // gx_embeds = embeds @ Wih[:, :512]^T + bih   (K=512)
        const int n0 = (bid - 1306) * BN;
        mainloop_hf(c1h + 3072, Wih, Ee, 3584, 2560, 0, n0,
                    c, dynh, tid, wm, wn, aOff, bOff);
        epilogue<0>(c, bih, gx, Bb, 3 * Hh, 0, n0, nullptr, nullptr, red,
                    tid, wm, wn, r, q, 0);
    }
}

// ============================================================================
// merged2: [0,24) gx-a (K=2048, EPI2) ; [24,274) pred-a (K=2048, EPI2)
//          274 CTAs, uniform 64 kb -> single balanced wave
// ============================================================================
__global__ __launch_bounds__(128, 2)
void k_merged2(const __half* __restrict__ c1h, const float* __restrict__ Wih,
               float* __restrict__ gx,
               const float* __restrict__ Wout, float* __restrict__ pred) {
    GEMM_PREAMBLE
    const int bid = blockIdx.x;
    if (bid < 24) {
        // gx += a @ Wih[:, 512:2560]^T   (a = c1h[:, 1024:3072])
        const int n0 = bid * BN;
        mainloop_hf(c1h + 1024, Wih + 512, 2 * Hh, 3584, 2560, 0, n0,
                    c, dynh, tid, wm, wn, aOff, bOff);
        epilogue<2>(c, nullptr, gx, Bb, 3 * Hh, 0, n0, nullptr, nullptr, red,
                    tid, wm, wn, r, q, 0);
    } else {
        const int n0 = (bid - 24) * BN;
        mainloop_hf(c1h + 1024, Wout + 1024, 2 * Hh, 3584, 3584, 0, n0,
                    c, dynh, tid, wm, wn, aOff, bOff);
        epilogue<2>(c, nullptr, pred, Bb, Vv, 0, n0, nullptr, nullptr, red,
                    tid, wm, wn, r, q, 0);
    }
}

// ============================================================================
// k_final: [0,128) gru (one b per CTA, arrives g_gru_flag) ;
//          [128,378) pred-hnew (waits g_gru_flag==128, then K=1024 EPI2)
// ============================================================================
__global__ __launch_bounds__(128, 2)
void k_final(const float* __restrict__ dh, const float* __restrict__ gx,
             const float* __restrict__ gh, float* __restrict__ hout,
             __half* __restrict__ c1h,
             const float* __restrict__ Wout, float* __restrict__ pred) {
    GEMM_PREAMBLE
    const int bid = blockIdx.x;
    if (bid < 128) {
        const int b = bid;
#pragma unroll
        for (int j = 0; j < 8; j++) {
            const int h = tid + j * 128;
            const float xr = gx[b * 3072 + h],        hr = gh[b * 3072 + h];
            const float xz = gx[b * 3072 + 1024 + h], hz = gh[b * 3072 + 1024 + h];
            const float xn = gx[b * 3072 + 2048 + h], hn = gh[b * 3072 + 2048 + h];
            const float rg = 1.f / (1.f + __expf(-(xr + hr)));
            const float zg = 1.f / (1.f + __expf(-(xz + hz)));
            const float ng = tanh_fast(xn + rg * hn);
            const float hv = (1.f - zg) * ng + zg * dh[b * Hh + h];
            hout[b * Hh + h] = hv;
            c1h[b * 3584 + h] = __float2half_rn(hv);
        }
        flag_arrive(&g_gru_flag);
    } else {
        flag_wait(&g_gru_flag, 128);
        const int n0 = (bid - 128) * BN;
        mainloop_hf(c1h, Wout, Hh, 3584, 3584, 0, n0,
                    c, dynh, tid, wm, wn, aOff, bOff);
        epilogue<2>(c, nullptr, pred, Bb, Vv, 0, n0, nullptr, nullptr, red,
                    tid, wm, wn, r, q, 0);
    }
}

// ============================================================================
// k_ctx: fused softmax + context. 256 blocks (2 per b), 512 threads.
// ============================================================================
__global__ __launch_bounds__(512)
void k_ctx(const float* __restrict__ part, const __half* __restrict__ ench,
           __half* __restrict__ c1h) {
    __shared__ float ssc[Ss], sred[Ss], salpha[Ss];
    const int b    = blockIdx.x >> 1;
    const int half = blockIdx.x & 1;
    const int tid  = threadIdx.x;

    if (tid < Ss) {
        float sc = 0.f;
#pragma unroll
        for (int p = 0; p < 8; p++) sc += part[p * (Ss * Bb) + tid * Bb + b];
        ssc[tid] = sc;
        sred[tid] = sc;
    }
    __syncthreads();
    for (int off = 64; off > 0; off >>= 1) {
        if (tid < off) sred[tid] = fmaxf(sred[tid], sred[tid + off]);
        __syncthreads();
    }
    const float mx = sred[0];
    __syncthreads();
    if (tid < Ss) {
        const float e = __expf(ssc[tid] - mx);
        salpha[tid] = e;
        sred[tid] = e;
    }
    __syncthreads();
    for (int off = 64; off > 0; off >>= 1) {
        if (tid < off) sred[tid] += sred[tid + off];
        __syncthreads();
    }
    const float inv = 1.f / sred[0];
    __syncthreads();
    if (tid < Ss) salpha[tid] *= inv;
    __syncthreads();

    const int col = half * 512 + tid;
    const __half2* base = (const __half2*)ench + (size_t)b * 1024 + col;
    float ax = 0.f, ay = 0.f;
#pragma unroll 8
    for (int s = 0; s < Ss; s++) {
        const float al = salpha[s];
        const float2 v = __half22float2(base[(size_t)s * (Bb * 1024)]);
        ax += al * v.x;
        ay += al * v.y;
    }
    *((__half2*)c1h + b * 1792 + 512 + col) = __floats2half2_rn(ax, ay);
}

// ---------------- launch ----------------------------------------------------
extern "C" void kernel_launch(void* const* d_in, const int* in_sizes, int n_in,
                              void* d_out, int out_size) {
    const int*   tl   = (const int*)d_in[0];
    const float* dh   = (const float*)d_in[1];
    const float* enc  = (const float*)d_in[2];
    const float* emb  = (const float*)d_in[3];
    const float* W1   = (const float*)d_in[4];
    const float* b1   = (const float*)d_in[5];
    const float* W2   = (const float*)d_in[6];
    // d_in[7] = b2 (softmax-invariant, skipped)
    const float* Wih  = (const float*)d_in[8];
    const float* Whh  = (const float*)d_in[9];
    const float* bih  = (const float*)d_in[10];
    const float* bhh  = (const float*)d_in[11];
    const float* Wout = (const float*)d_in[12];
    const float* bout = (const float*)d_in[13];

    float* pred = (float*)d_out;                 // [128, 32000]
    float* hout = pred + (size_t)Bb * Vv;        // [128, 1024]

    __half *ench, *w1e, *dhh, *c1h;
    float *hbp, *part, *gx, *gh;
    cudaGetSymbolAddress((void**)&ench,  g_ench);
    cudaGetSymbolAddress((void**)&w1e,   g_w1e);
    cudaGetSymbolAddress((void**)&dhh,   g_dhh);
    cudaGetSymbolAddress((void**)&c1h,   g_c1h);
    cudaGetSymbolAddress((void**)&hbp,   g_hb);
    cudaGetSymbolAddress((void**)&part,  g_part);
    cudaGetSymbolAddress((void**)&gx,    g_gx);
    cudaGetSymbolAddress((void**)&gh,    g_gh);

    cudaFuncSetAttribute(k_merged1, cudaFuncAttributeMaxDynamicSharedMemorySize, DSMEM_BYTES);
    cudaFuncSetAttribute(k_merged2, cudaFuncAttributeMaxDynamicSharedMemorySize, DSMEM_BYTES);
    cudaFuncSetAttribute(k_final,   cudaFuncAttributeMaxDynamicSharedMemorySize, DSMEM_BYTES);

    // 1) prep: conversions + embeddings + flag reset (no smem, full occupancy)
    k_prep<<<PENC + PW1 + PDH + PEMB, 256>>>(enc, ench, W1, w1e, dh, dhh,
                                             tl, emb, c1h);

    // 2) merged: hb (8) + energy (1024) + pred-embeds (250) + gh (24) + gx-embeds (24)
    k_merged1<<<1330, 128, DSMEM_BYTES>>>(ench, w1e, dh, W1, b1, hbp,
                                          W2, part,
                                          c1h, Wout, bout, pred,
                                          dhh, Whh, bhh, gh,
                                          Wih, bih, gx);

    // 3) fused softmax + context -> c1h[:, 1024:3072]  (2 blocks per b)
    k_ctx<<<2 * Bb, 512>>>(part, ench, c1h);

    // 4) merged: gx += a-part (24) + pred += a-part (250) — uniform single wave
    k_merged2<<<274, 128, DSMEM_BYTES>>>(c1h, Wih, gx, Wout, pred);

    // 5) final: gru (128) + pred += h_new @ Wout[:, :1024]^T (250)
    k_final<<<378, 128, DSMEM_BYTES>>>(dh, gx, gh, hout, c1h, Wout, pred);
}

// round 14
// speedup vs baseline: 1.1220x; 1.0101x over previous
#include <cuda_runtime.h>
#include <cuda_fp16.h>
#include <cstdint>

// Problem constants
#define Bb 128
#define Ss 128
#define Hh 1024
#define Ee 512
#define Vv 32000

// fp16 GEMM tile config: CTA 128x128, 4 warps, warp tile 64x64, BK=32, 3 stages
#define BM 128
#define BN 128
#define BK 32
#define SAH 40                       // padded smem row stride in halfs (80B rows)
#define TILE_H (BM * SAH)            // 5120 halfs per A or B tile
#define STAGE_H (2 * TILE_H)         // 10240 halfs per stage
#define NSTG 3
#define DSMEM_BYTES (NSTG * STAGE_H * 2)   // 61440

// ---------------- scratch (device globals; no allocation allowed) ----------
__device__ __align__(256) __half g_ench[(size_t)Ss * Bb * 2 * Hh]; // enc fp16
__device__ __align__(256) __half g_w1e[Hh * 2 * Hh];               // W1[:, :2048] fp16
__device__ __align__(256) __half g_dhh[Bb * Hh];                   // dh fp16
__device__ __align__(256) __half g_c1h[Bb * 3584];                 // [h | a | emb] fp16
__device__ __align__(256) float  g_hb[Bb * Hh];
__device__ __align__(256) float  g_part[8 * Ss * Bb];
__device__ __align__(256) float  g_gx[Bb * 3 * Hh];
__device__ __align__(256) float  g_gh[Bb * 3 * Hh];
__device__ int g_hb_flag;    // counts hb producer CTAs (target 8)
__device__ int g_gx_flag;    // counts gx-a producer CTAs (target 24)
__device__ int g_gru_flag;   // counts gru producer CTAs (target 128)

// ---------------- helpers ---------------------------------------------------
__device__ __forceinline__ uint32_t smem_u32(const void* p) {
    uint32_t a;
    asm("{ .reg .u64 t; cvta.to.shared.u64 t, %1; cvt.u32.u64 %0, t; }"
        : "=r"(a) : "l"(p));
    return a;
}

__device__ __forceinline__ void mma_f16(float* c,
                                        uint32_t a0, uint32_t a1, uint32_t a2, uint32_t a3,
                                        uint32_t b0, uint32_t b1) {
    asm volatile(
        "mma.sync.aligned.m16n8k16.row.col.f32.f16.f16.f32 "
        "{%0,%1,%2,%3}, {%4,%5,%6,%7}, {%8,%9}, {%0,%1,%2,%3};"
        : "+f"(c[0]), "+f"(c[1]), "+f"(c[2]), "+f"(c[3])
        : "r"(a0), "r"(a1), "r"(a2), "r"(a3), "r"(b0), "r"(b1));
}

__device__ __forceinline__ void ldsm4(uint32_t& r0, uint32_t& r1,
                                      uint32_t& r2, uint32_t& r3, uint32_t addr) {
    asm volatile("ldmatrix.sync.aligned.m8n8.x4.shared.b16 {%0,%1,%2,%3}, [%4];"
                 : "=r"(r0), "=r"(r1), "=r"(r2), "=r"(r3) : "r"(addr));
}

__device__ __forceinline__ void cp16u(uint32_t dst, const void* src) {
    asm volatile("cp.async.ca.shared.global [%0], [%1], 16;" :: "r"(dst), "l"(src));
}
__device__ __forceinline__ void cp_commit() {
    asm volatile("cp.async.commit_group;" ::: "memory");
}
template <int N>
__device__ __forceinline__ void cp_wait() {
    asm volatile("cp.async.wait_group %0;" :: "n"(N) : "memory");
}

__device__ __forceinline__ float tanh_fast(float x) {
    x = fminf(10.f, fmaxf(-10.f, x));
    const float t = __expf(2.f * x);
    return (t - 1.f) / (t + 1.f);
}

__device__ __forceinline__ uint2 cvt_f4_h4(float4 v) {
    half2 h0 = __floats2half2_rn(v.x, v.y);
    half2 h1 = __floats2half2_rn(v.z, v.w);
    uint2 u;
    u.x = *reinterpret_cast<uint32_t*>(&h0);
    u.y = *reinterpret_cast<uint32_t*>(&h1);
    return u;
}

// producer arrive: all threads fence own writes, sync, one thread bumps flag
__device__ __forceinline__ void flag_arrive(int* flag) {
    __threadfence();
    __syncthreads();
    if (threadIdx.x == 0) atomicAdd(flag, 1);
}
// consumer wait: spin until flag reaches target, then fence for acquire
__device__ __forceinline__ void flag_wait(int* flag, int target) {
    if (threadIdx.x == 0) {
        while (*(volatile int*)flag < target) {}
    }
    __syncthreads();
    __threadfence();
}

// ---------------- GEMM compute body: ldmatrix + m16n8k16 --------------------
__device__ __forceinline__ void compute_kb(uint32_t aBase, uint32_t bBase,
                                           float c[4][8][4], int wm, int wn,
                                           uint32_t aOff, uint32_t bOff) {
#pragma unroll
    for (int ks = 0; ks < 2; ks++) {
        const uint32_t k0b = ks * 32;   // 16 halfs
        uint32_t af[4][4], bf[4][4];
#pragma unroll
        for (int mf = 0; mf < 4; mf++)
            ldsm4(af[mf][0], af[mf][1], af[mf][2], af[mf][3],
                  aBase + (uint32_t)(((wm * 64 + mf * 16) * SAH) * 2) + k0b + aOff);
#pragma unroll
        for (int np = 0; np < 4; np++)
            ldsm4(bf[np][0], bf[np][1], bf[np][2], bf[np][3],
                  bBase + (uint32_t)(((wn * 64 + np * 16) * SAH) * 2) + k0b + bOff);
#pragma unroll
        for (int nf = 0; nf < 8; nf++) {
            const uint32_t b0 = bf[nf >> 1][(nf & 1) << 1];
            const uint32_t b1 = bf[nf >> 1][((nf & 1) << 1) + 1];
#pragma unroll
            for (int mf = 0; mf < 4; mf++)
                mma_f16(c[mf][nf], af[mf][0], af[mf][1], af[mf][2], af[mf][3], b0, b1);
        }
    }
}

// ---------------- epilogues --------------------------------------------------
// EPI 0: out = acc + bias   EPI 1: energy reduce   EPI 2: out += acc
template <int EPI>
__device__ __forceinline__ void epilogue(float c[4][8][4],
                                         const float* __restrict__ bias,
                                         float* __restrict__ out,
                                         int M, int ldc, int m0, int n0,
                                         const float* __restrict__ hb,
                                         const float* __restrict__ W2,
                                         float (*red)[2],
                                         int tid, int wm, int wn, int r, int q,
                                         int bx) {
    if (EPI == 0 || EPI == 2) {
#pragma unroll
        for (int mf = 0; mf < 4; mf++)
#pragma unroll
            for (int rr = 0; rr < 2; rr++) {
                const int mg = m0 + wm * 64 + mf * 16 + rr * 8 + r;
#pragma unroll
                for (int nf = 0; nf < 8; nf++) {
                    const int ng = n0 + wn * 64 + nf * 8 + q * 2;
                    float* p = &out[(size_t)mg * ldc + ng];
                    float2 v;
                    if (EPI == 0) {
                        v.x = c[mf][nf][rr * 2 + 0] + bias[ng];
                        v.y = c[mf][nf][rr * 2 + 1] + bias[ng + 1];
                    } else {
                        float2 o = *(float2*)p;
                        v.x = o.x + c[mf][nf][rr * 2 + 0];
                        v.y = o.y + c[mf][nf][rr * 2 + 1];
                    }
                    *(float2*)p = v;
                }
            }
    } else {
        float rs[4][2];
#pragma unroll
        for (int mf = 0; mf < 4; mf++)
#pragma unroll
            for (int rr = 0; rr < 2; rr++) {
                const int row = wm * 64 + mf * 16 + rr * 8 + r; // == b
                float acc = 0.f;
#pragma unroll
                for (int nf = 0; nf < 8; nf++) {
                    const int ng = n0 + wn * 64 + nf * 8 + q * 2;
                    const float h0 = hb[row * Hh + ng];
                    const float h1 = hb[row * Hh + ng + 1];
                    acc += tanh_fast(c[mf][nf][rr * 2 + 0] + h0) * W2[ng];
                    acc += tanh_fast(c[mf][nf][rr * 2 + 1] + h1) * W2[ng + 1];
                }
                rs[mf][rr] = acc;
            }
#pragma unroll
        for (int mf = 0; mf < 4; mf++)
#pragma unroll
            for (int rr = 0; rr < 2; rr++) {
                rs[mf][rr] += __shfl_xor_sync(0xffffffffu, rs[mf][rr], 1);
                rs[mf][rr] += __shfl_xor_sync(0xffffffffu, rs[mf][rr], 2);
            }
        if (q == 0) {
#pragma unroll
            for (int mf = 0; mf < 4; mf++)
#pragma unroll
                for (int rr = 0; rr < 2; rr++)
                    red[wm * 64 + mf * 16 + rr * 8 + r][wn] = rs[mf][rr];
        }
        __syncthreads();
        if (tid < BM)
            out[(size_t)bx * M + m0 + tid] = red[tid][0] + red[tid][1];
    }
}

// ---------------- mainloops (device functions, explicit m0/n0) --------------
// HH: A fp16, B fp16 (both cp.async)
__device__ __forceinline__ void mainloop_hh(const __half* __restrict__ A,
                                            const __half* __restrict__ Bw,
                                            int K, int lda, int ldb,
                                            int m0, int n0,
                                            float c[4][8][4], __half* dynh,
                                            int tid, int wm, int wn,
                                            uint32_t aOff, uint32_t bOff) {
    const int nK = K / BK;
    const uint32_t dynU = smem_u32(dynh);
    auto cpfill = [&](int kb, int stg) {
        const uint32_t base = dynU + stg * (STAGE_H * 2);
        const int ko = kb * BK;
#pragma unroll
        for (int h = 0; h < 4; h++) {
            const int cc = tid + h * 128;
            const int row = cc >> 2, g = cc & 3;
            cp16u(base + (row * SAH + g * 8) * 2,
                  A + (size_t)(m0 + row) * lda + ko + g * 8);
            cp16u(base + TILE_H * 2 + (row * SAH + g * 8) * 2,
                  Bw + (size_t)(n0 + row) * ldb + ko + g * 8);
        }
    };
    cpfill(0, 0); cp_commit();
    cpfill(1, 1); cp_commit();
    cp_wait<1>(); __syncthreads();
    int stg = 0;
    for (int kb = 0; kb < nK; kb++) {
        if (kb + 2 < nK) {
            int s2 = stg + 2; if (s2 >= NSTG) s2 -= NSTG;
            cpfill(kb + 2, s2);
        }
        cp_commit();
        const uint32_t aB = dynU + stg * (STAGE_H * 2);
        compute_kb(aB, aB + TILE_H * 2, c, wm, wn, aOff, bOff);
        cp_wait<1>(); __syncthreads();
        if (++stg == NSTG) stg = 0;
    }
}

// HF: A fp16 (cp.async), B fp32 (LDG -> cvt -> STS)
__device__ __forceinline__ void mainloop_hf(const __half* __restrict__ A,
                                            const float* __restrict__ Bw,
                                            int K, int lda, int ldb,
                                            int m0, int n0,
                                            float c[4][8][4], __half* dynh,
                                            int tid, int wm, int wn,
                                            uint32_t aOff, uint32_t bOff) {
    const int nK = K / BK;
    const uint32_t dynU = smem_u32(dynh);
    int rowv[8], gv[8];
#pragma unroll
    for (int h = 0; h < 8; h++) {
        const int idx = tid + h * 128;
        rowv[h] = idx >> 3;
        gv[h]   = idx & 7;
    }
    uint2 sb[8];
    auto cpA = [&](int kb, int stg) {
        const uint32_t base = dynU + stg * (STAGE_H * 2);
        const int ko = kb * BK;
#pragma unroll
        for (int h = 0; h < 4; h++) {
            const int cc = tid + h * 128;
            const int row = cc >> 2, g = cc & 3;
            cp16u(base + (row * SAH + g * 8) * 2,
                  A + (size_t)(m0 + row) * lda + ko + g * 8);
        }
    };
    auto ldB = [&](int kb) {
        const int ko = kb * BK;
#pragma unroll
        for (int h = 0; h < 8; h++)
            sb[h] = cvt_f4_h4(*(const float4*)(Bw + (size_t)(n0 + rowv[h]) * ldb
                                               + ko + gv[h] * 4));
    };
    auto stsB = [&](int stg) {
        __half* D = dynh + stg * STAGE_H + TILE_H;
#pragma unroll
        for (int h = 0; h < 8; h++)
            *(uint2*)(D + rowv[h] * SAH + gv[h] * 4) = sb[h];
    };
    cpA(0, 0); cp_commit();
    cpA(1, 1); cp_commit();
    ldB(0); stsB(0); ldB(1);
    cp_wait<1>(); __syncthreads();
    int stg = 0;
    for (int kb = 0; kb < nK; kb++) {
        int w = stg + 1; if (w == NSTG) w = 0;
        if (kb + 1 < nK) stsB(w);
        if (kb + 2 < nK) {
            int s2 = stg + 2; if (s2 >= NSTG) s2 -= NSTG;
            cpA(kb + 2, s2);
            ldB(kb + 2);
        }
        cp_commit();
        const uint32_t aB = dynU + stg * (STAGE_H * 2);
        compute_kb(aB, aB + TILE_H * 2, c, wm, wn, aOff, bOff);
        cp_wait<1>(); __syncthreads();
        stg = w;
    }
}

// FF: A fp32 and B fp32, both LDG -> cvt -> STS
__device__ __forceinline__ void mainloop_ff(const float* __restrict__ A,
                                            const float* __restrict__ Bw,
                                            int K, int lda, int ldb,
                                            int m0, int n0,
                                            float c[4][8][4], __half* dynh,
                                            int tid, int wm, int wn,
                                            uint32_t aOff, uint32_t bOff) {
    const int nK = K / BK;
    int rowv[8], gv[8];
#pragma unroll
    for (int h = 0; h < 8; h++) {
        const int idx = tid + h * 128;
        rowv[h] = idx >> 3;
        gv[h]   = idx & 7;
    }
    uint2 sa[8], sb[8];
    auto ldAB = [&](int kb) {
        const int ko = kb * BK;
#pragma unroll
        for (int h = 0; h < 8; h++) {
            sa[h] = cvt_f4_h4(*(const float4*)(A  + (size_t)(m0 + rowv[h]) * lda
                                               + ko + gv[h] * 4));
            sb[h] = cvt_f4_h4(*(const float4*)(Bw + (size_t)(n0 + rowv[h]) * ldb
                                               + ko + gv[h] * 4));
        }
    };
    auto stsAB = [&](int stg) {
        __half* D = dynh + stg * STAGE_H;
#pragma unroll
        for (int h = 0; h < 8; h++) {
            *(uint2*)(D + rowv[h] * SAH + gv[h] * 4)          = sa[h];
            *(uint2*)(D + TILE_H + rowv[h] * SAH + gv[h] * 4) = sb[h];
        }
    };
    ldAB(0); stsAB(0);
    if (nK > 1) ldAB(1);
    __syncthreads();
    int stg = 0;
    for (int kb = 0; kb < nK; kb++) {
        int w = stg + 1; if (w == NSTG) w = 0;
        if (kb + 1 < nK) stsAB(w);
        if (kb + 2 < nK) ldAB(kb + 2);
        compute_kb(smem_u32(dynh) + stg * (STAGE_H * 2),
                   smem_u32(dynh) + stg * (STAGE_H * 2) + TILE_H * 2,
                   c, wm, wn, aOff, bOff);
        __syncthreads();
        stg = w;
    }
}

#define GEMM_PREAMBLE \
    extern __shared__ __align__(16) __half dynh[]; \
    __shared__ float red[BM][2]; \
    const int tid = threadIdx.x, lane = tid & 31, wid = tid >> 5; \
    const int wm = wid >> 1, wn = wid & 1, r = lane >> 2, q = lane & 3; \
    const uint32_t aOff = (uint32_t)((((lane & 15) * SAH) + (lane >> 4) * 8) * 2); \
    const uint32_t bOff = (uint32_t)(((((lane >> 4) * 8 + (lane & 7)) * SAH) \
                                      + ((lane >> 3) & 1) * 8) * 2); \
    float c[4][8][4]; \
    _Pragma("unroll") for (int i = 0; i < 4; i++) \
    _Pragma("unroll") for (int j = 0; j < 8; j++) \
    _Pragma("unroll") for (int k = 0; k < 4; k++) c[i][j][k] = 0.f;

// ============================================================================
// k_prep: lightweight (no smem, 256 threads) cvt + embed in one launch
//   [0, 2048)    enc -> fp16    (4096 f4 per block; 8,388,608 f4 total)
//   [2048, 2304) W1[:, :2048] -> fp16 (2048 f4 per block)
//   [2304, 2312) dh -> fp16     (4096 f4 per block)
//   [2312, 2440) embeddings     (one b per block)
//   block 0 thread 0 also resets the producer flags for this replay.
// ============================================================================
#define PENC 2048
#define PW1  256
#define PDH  8
#define PEMB 128

__global__ __launch_bounds__(256)
void k_prep(const float* __restrict__ enc, __half* __restrict__ ench,
            const float* __restrict__ W1, __half* __restrict__ w1e,
            const float* __restrict__ dh, __half* __restrict__ dhh,
            const int* __restrict__ tl, const float* __restrict__ emb,
            __half* __restrict__ c1h) {
    const int bid = blockIdx.x;
    const int tid = threadIdx.x;
    if (bid == 0 && tid == 0) { g_hb_flag = 0; g_gx_flag = 0; g_gru_flag = 0; }
    if (bid < PENC) {
        const float4* src = (const float4*)enc;
        uint2* dst = (uint2*)ench;
        const int base = bid * 4096 + tid;
#pragma unroll
        for (int j = 0; j < 16; j++)
            dst[base + j * 256] = cvt_f4_h4(src[base + j * 256]);
    } else if (bid < PENC + PW1) {
        const int base = (bid - PENC) * 2048 + tid;
#pragma unroll
        for (int j = 0; j < 8; j++) {
            const int i = base + j * 256;           // f4 index in w1e
            const int row = i >> 9, c4 = i & 511;
            float4 v = *(const float4*)(W1 + (size_t)row * 3072 + c4 * 4);
            *(uint2*)(w1e + row * 2048 + c4 * 4) = cvt_f4_h4(v);
        }
    } else if (bid < PENC + PW1 + PDH) {
        const float4* src = (const float4*)dh;
        uint2* dst = (uint2*)dhh;
        const int base = (bid - PENC - PW1) * 4096 + tid;
#pragma unroll
        for (int j = 0; j < 16; j++)
            dst[base + j * 256] = cvt_f4_h4(src[base + j * 256]);
    } else {
        const int b = bid - PENC - PW1 - PDH;
        const size_t rowoff = (size_t)tl[b] * Ee;
#pragma unroll
        for (int j = 0; j < 2; j++) {
            const int e = tid + j * 256;
            c1h[b * 3584 + 3072 + e] = __float2half_rn(emb[rowoff + e]);
        }
    }
}

// ============================================================================
// merged1: [0,8) hb (ff, EPI0, arrives g_hb_flag) ;
//          [8,1032) energy (hh, EPI1, waits g_hb_flag==8) ;
//          [1032,1282) pred-embeds (hf, EPI0) ;
//          [1282,1306) gh (hf, EPI0) ; [1306,1330) gx-embeds (hf, EPI0)
// ============================================================================
__global__ __launch_bounds__(128, 2)
void k_merged1(const __half* __restrict__ ench, const __half* __restrict__ w1e,
               const float* __restrict__ dh, const float* __restrict__ W1,
               const float* __restrict__ b1, float* __restrict__ hbp,
               const float* __restrict__ W2, float* __restrict__ part,
               const __half* __restrict__ c1h, const float* __restrict__ Wout,
               const float* __restrict__ bout, float* __restrict__ pred,
               const __half* __restrict__ dhh, const float* __restrict__ Whh,
               const float* __restrict__ bhh, float* __restrict__ gh,
               const float* __restrict__ Wih, const float* __restrict__ bih,
               float* __restrict__ gx) {
    GEMM_PREAMBLE
    const int bid = blockIdx.x;
    if (bid < 8) {
        // hb = dh @ W1[:, 2048:3072]^T + b1  (fp32 inputs, K=1024)
        const int n0 = bid * BN;
        mainloop_ff(dh, W1 + 2048, Hh, Hh, 3 * Hh, 0, n0,
                    c, dynh, tid, wm, wn, aOff, bOff);
        epilogue<0>(c, b1, hbp, Bb, Hh, 0, n0, nullptr, nullptr, red,
                    tid, wm, wn, r, q, 0);
        flag_arrive(&g_hb_flag);
    } else if (bid < 1032) {
        const int idx = bid - 8;
        const int n0 = (idx & 7) * BN, m0 = (idx >> 3) * BM;
        mainloop_hh(ench, w1e, 2 * Hh, 2 * Hh, 2 * Hh, m0, n0,
                    c, dynh, tid, wm, wn, aOff, bOff);
        flag_wait(&g_hb_flag, 8);   // hb ready long before any epilogue
        epilogue<1>(c, nullptr, part, Ss * Bb, 0, m0, n0, hbp, W2, red,
                    tid, wm, wn, r, q, idx & 7);
    } else if (bid < 1282) {
        const int n0 = (bid - 1032) * BN;
        mainloop_hf(c1h + 3072, Wout + 3072, Ee, 3584, 3584, 0, n0,
                    c, dynh, tid, wm, wn, aOff, bOff);
        epilogue<0>(c, bout, pred, Bb, Vv, 0, n0, nullptr, nullptr, red,
                    tid, wm, wn, r, q, 0);
    } else if (bid < 1306) {
        const int n0 = (bid - 1282) * BN;
        mainloop_hf(dhh, Whh, Hh, Hh, Hh, 0, n0,
                    c, dynh, tid, wm, wn, aOff, bOff);
        epilogue<0>(c, bhh, gh, Bb, 3 * Hh, 0, n0, nullptr, nullptr, red,
                    tid, wm, wn, r, q, 0);
    } else {
        // gx_embeds = embeds @ Wih[:, :512]^T + bih   (K=512)
        const int n0 = (bid - 1306) * BN;
        mainloop_hf(c1h + 3072, Wih, Ee, 3584, 2560, 0, n0,
                    c, dynh, tid, wm, wn, aOff, bOff);
        epilogue<0>(c, bih, gx, Bb, 3 * Hh, 0, n0, nullptr, nullptr, red,
                    tid, wm, wn, r, q, 0);
    }
}

// ============================================================================
// k_tail: fused merged2 + gru + pred-hnew (in-grid flag dependencies)
//   [0,24)    gx-a (K=2048, EPI2 gx), arrives g_gx_flag
//   [24,274)  pred-a (K=2048, EPI2 pred)
//   [274,402) gru (one b per CTA), waits g_gx_flag==24, arrives g_gru_flag
//   [402,652) pred-hnew (K=1024, EPI2 pred), waits g_gru_flag==128
// Wave 1 (296 slots) holds ALL gx producers -> no deadlock; gru/pred-hnew
// stream in as earlier CTAs retire.
// ============================================================================
__global__ __launch_bounds__(128, 2)
void k_tail(const __half* __restrict__ c1h, const float* __restrict__ Wih,
            float* __restrict__ gx,
            const float* __restrict__ Wout, float* __restrict__ pred,
            const float* __restrict__ dh, const float* __restrict__ gh,
            float* __restrict__ hout, __half* __restrict__ c1h_w) {
    GEMM_PREAMBLE
    const int bid = blockIdx.x;
    if (bid < 24) {
        // gx += a @ Wih[:, 512:2560]^T   (a = c1h[:, 1024:3072])
        const int n0 = bid * BN;
        mainloop_hf(c1h + 1024, Wih + 512, 2 * Hh, 3584, 2560, 0, n0,
                    c, dynh, tid, wm, wn, aOff, bOff);
        epilogue<2>(c, nullptr, gx, Bb, 3 * Hh, 0, n0, nullptr, nullptr, red,
                    tid, wm, wn, r, q, 0);
        flag_arrive(&g_gx_flag);
    } else if (bid < 274) {
        const int n0 = (bid - 24) * BN;
        mainloop_hf(c1h + 1024, Wout + 1024, 2 * Hh, 3584, 3584, 0, n0,
                    c, dynh, tid, wm, wn, aOff, bOff);
        epilogue<2>(c, nullptr, pred, Bb, Vv, 0, n0, nullptr, nullptr, red,
                    tid, wm, wn, r, q, 0);
    } else if (bid < 402) {
        flag_wait(&g_gx_flag, 24);
        const int b = bid - 274;
#pragma unroll
        for (int j = 0; j < 8; j++) {
            const int h = tid + j * 128;
            const float xr = gx[b * 3072 + h],        hr = gh[b * 3072 + h];
            const float xz = gx[b * 3072 + 1024 + h], hz = gh[b * 3072 + 1024 + h];
            const float xn = gx[b * 3072 + 2048 + h], hn = gh[b * 3072 + 2048 + h];
            const float rg = 1.f / (1.f + __expf(-(xr + hr)));
            const float zg = 1.f / (1.f + __expf(-(xz + hz)));
            const float ng = tanh_fast(xn + rg * hn);
            const float hv = (1.f - zg) * ng + zg * dh[b * Hh + h];
            hout[b * Hh + h] = hv;
            c1h_w[b * 3584 + h] = __float2half_rn(hv);
        }
        flag_arrive(&g_gru_flag);
    } else {
        flag_wait(&g_gru_flag, 128);
        const int n0 = (bid - 402) * BN;
        mainloop_hf(c1h, Wout, Hh, 3584, 3584, 0, n0,
                    c, dynh, tid, wm, wn, aOff, bOff);
        epilogue<2>(c, nullptr, pred, Bb, Vv, 0, n0, nullptr, nullptr, red,
                    tid, wm, wn, r, q, 0);
    }
}

// ============================================================================
// k_ctx: fused softmax + context. 256 blocks (2 per b), 512 threads.
// ============================================================================
__global__ __launch_bounds__(512)
void k_ctx(const float* __restrict__ part, const __half* __restrict__ ench,
           __half* __restrict__ c1h) {
    __shared__ float ssc[Ss], sred[Ss], salpha[Ss];
    const int b    = blockIdx.x >> 1;
    const int half = blockIdx.x & 1;
    const int tid  = threadIdx.x;

    if (tid < Ss) {
        float sc = 0.f;
#pragma unroll
        for (int p = 0; p < 8; p++) sc += part[p * (Ss * Bb) + tid * Bb + b];
        ssc[tid] = sc;
        sred[tid] = sc;
    }
    __syncthreads();
    for (int off = 64; off > 0; off >>= 1) {
        if (tid < off) sred[tid] = fmaxf(sred[tid], sred[tid + off]);
        __syncthreads();
    }
    const float mx = sred[0];
    __syncthreads();
    if (tid < Ss) {
        const float e = __expf(ssc[tid] - mx);
        salpha[tid] = e;
        sred[tid] = e;
    }
    __syncthreads();
    for (int off = 64; off > 0; off >>= 1) {
        if (tid < off) sred[tid] += sred[tid + off];
        __syncthreads();
    }
    const float inv = 1.f / sred[0];
    __syncthreads();
    if (tid < Ss) salpha[tid] *= inv;
    __syncthreads();

    const int col = half * 512 + tid;
    const __half2* base = (const __half2*)ench + (size_t)b * 1024 + col;
    float ax = 0.f, ay = 0.f;
#pragma unroll 8
    for (int s = 0; s < Ss; s++) {
        const float al = salpha[s];
        const float2 v = __half22float2(base[(size_t)s * (Bb * 1024)]);
        ax += al * v.x;
        ay += al * v.y;
    }
    *((__half2*)c1h + b * 1792 + 512 + col) = __floats2half2_rn(ax, ay);
}

// ---------------- launch ----------------------------------------------------
extern "C" void kernel_launch(void* const* d_in, const int* in_sizes, int n_in,
                              void* d_out, int out_size) {
    const int*   tl   = (const int*)d_in[0];
    const float* dh   = (const float*)d_in[1];
    const float* enc  = (const float*)d_in[2];
    const float* emb  = (const float*)d_in[3];
    const float* W1   = (const float*)d_in[4];
    const float* b1   = (const float*)d_in[5];
    const float* W2   = (const float*)d_in[6];
    // d_in[7] = b2 (softmax-invariant, skipped)
    const float* Wih  = (const float*)d_in[8];
    const float* Whh  = (const float*)d_in[9];
    const float* bih  = (const float*)d_in[10];
    const float* bhh  = (const float*)d_in[11];
    const float* Wout = (const float*)d_in[12];
    const float* bout = (const float*)d_in[13];

    float* pred = (float*)d_out;                 // [128, 32000]
    float* hout = pred + (size_t)Bb * Vv;        // [128, 1024]

    __half *ench, *w1e, *dhh, *c1h;
    float *hbp, *part, *gx, *gh;
    cudaGetSymbolAddress((void**)&ench,  g_ench);
    cudaGetSymbolAddress((void**)&w1e,   g_w1e);
    cudaGetSymbolAddress((void**)&dhh,   g_dhh);
    cudaGetSymbolAddress((void**)&c1h,   g_c1h);
    cudaGetSymbolAddress((void**)&hbp,   g_hb);
    cudaGetSymbolAddress((void**)&part,  g_part);
    cudaGetSymbolAddress((void**)&gx,    g_gx);
    cudaGetSymbolAddress((void**)&gh,    g_gh);

    cudaFuncSetAttribute(k_merged1, cudaFuncAttributeMaxDynamicSharedMemorySize, DSMEM_BYTES);
    cudaFuncSetAttribute(k_tail,    cudaFuncAttributeMaxDynamicSharedMemorySize, DSMEM_BYTES);

    // 1) prep: conversions + embeddings + flag reset (no smem, full occupancy)
    k_prep<<<PENC + PW1 + PDH + PEMB, 256>>>(enc, ench, W1, w1e, dh, dhh,
                                             tl, emb, c1h);

    // 2) merged: hb (8) + energy (1024) + pred-embeds (250) + gh (24) + gx-embeds (24)
    k_merged1<<<1330, 128, DSMEM_BYTES>>>(ench, w1e, dh, W1, b1, hbp,
                                          W2, part,
                                          c1h, Wout, bout, pred,
                                          dhh, Whh, bhh, gh,
                                          Wih, bih, gx);

    // 3) fused softmax + context -> c1h[:, 1024:3072]  (2 blocks per b)
    k_ctx<<<2 * Bb, 512>>>(part, ench, c1h);

    // 4) tail: gx-a (24) + pred-a (250) + gru (128, flag) + pred-hnew (250, flag)
    k_tail<<<652, 128, DSMEM_BYTES>>>(c1h, Wih, gx, Wout, pred,
                                      dh, gh, hout, c1h);
}